// round 10
// baseline (speedup 1.0000x reference)
#include <cuda_runtime.h>
#include <math.h>

#define BB   2
#define SS   2048
#define DD   2048
#define HQ   16
#define HKV  4
#define HD   128
#define KVD  512
#define MM   (BB*SS)
#define NT   (SS/64)

// Scratch (device globals)
__device__ float g_Q[(size_t)MM * DD];    // [token][d]  d 16-perm, scaled
__device__ float g_K[(size_t)MM * KVD];   // [token][gd] d 16-perm
__device__ float g_V[(size_t)MM * KVD];   // [token][gd] plain
__device__ float g_Vt[(size_t)BB * KVD * SS]; // [b*512+gd][s] s 16-perm
__device__ float g_H[(size_t)MM * DD];    // tf32-rounded, k 16-perm
__device__ float g_Wq[(size_t)DD * DD];   // [k][n] tf32-rounded
__device__ float g_Wk[(size_t)DD * KVD];
__device__ float g_Wv[(size_t)DD * KVD];

__device__ __forceinline__ unsigned f2tf(float x) {
    unsigned r;
    asm("cvt.rna.tf32.f32 %0, %1;" : "=r"(r) : "f"(x));
    return r;
}
__device__ __forceinline__ float f2tff(float x) { return __uint_as_float(f2tf(x)); }

__device__ __forceinline__ void mma_tf32(float c[4], const unsigned a[4], const unsigned b[2]) {
    asm volatile(
        "mma.sync.aligned.m16n8k8.row.col.f32.tf32.tf32.f32 "
        "{%0,%1,%2,%3},{%4,%5,%6,%7},{%8,%9},{%0,%1,%2,%3};"
        : "+f"(c[0]), "+f"(c[1]), "+f"(c[2]), "+f"(c[3])
        : "r"(a[0]), "r"(a[1]), "r"(a[2]), "r"(a[3]), "r"(b[0]), "r"(b[1]));
}

#define CP16(dst, src) \
    asm volatile("cp.async.cg.shared.global [%0], [%1], 16;" :: "r"(dst), "l"(src))
#define CPCOMMIT() asm volatile("cp.async.commit_group;")
#define CPWAIT(N)  asm volatile("cp.async.wait_group %0;" :: "n"(N))

#define MBAR_INIT(addr, cnt) \
    asm volatile("mbarrier.init.shared.b64 [%0], %1;" :: "r"(addr), "r"(cnt) : "memory")
#define MBAR_ARRIVE(addr) \
    asm volatile("mbarrier.arrive.shared.b64 _, [%0];" :: "r"(addr) : "memory")
#define CPASYNC_MBAR_ARRIVE(addr) \
    asm volatile("cp.async.mbarrier.arrive.noinc.shared.b64 [%0];" :: "r"(addr) : "memory")

#define MBAR_WAIT(addr, par) do { \
    unsigned _m = (addr), _p = (par), _d; \
    asm volatile("{\n\t.reg .pred p;\n\t" \
        "mbarrier.try_wait.parity.acquire.cta.shared::cta.b64 p, [%1], %2;\n\t" \
        "selp.b32 %0, 1, 0, p;\n\t}" : "=r"(_d) : "r"(_m), "r"(_p) : "memory"); \
    if (!_d) { \
        asm volatile("{\n\t.reg .pred P1;\n\t" \
            "WL%=:\n\t" \
            "mbarrier.try_wait.parity.acquire.cta.shared::cta.b64 P1, [%0], %1, 0x989680;\n\t" \
            "@P1 bra.uni WD%=;\n\t" \
            "bra.uni WL%=;\n\t" \
            "WD%=:\n\t}" :: "r"(_m), "r"(_p) : "memory"); \
    } \
} while (0)

// ---------------------------------------------------------------------------
// Fused pre-pass (launch #1). z=0: H -> tf32 + 16-perm (4x4 transpose per
// 16-group). z=1..3: weights -> tf32, natural order.
// ---------------------------------------------------------------------------
__global__ void cvt_fused(
    float* __restrict__ Hd, const float* __restrict__ Hs,
    float* __restrict__ Wqd, const float* __restrict__ Wqs,
    float* __restrict__ Wkd, const float* __restrict__ Wks,
    float* __restrict__ Wvd, const float* __restrict__ Wvs)
{
    const int z = blockIdx.z;
    int i = blockIdx.x * blockDim.x + threadIdx.x;
    const int stride = gridDim.x * blockDim.x;
    if (z == 0) {
        const int n16 = (int)((size_t)MM * DD / 16);
        for (; i < n16; i += stride) {
            const float4* s = (const float4*)Hs + 4 * (size_t)i;
            float4 a = s[0], b = s[1], c = s[2], d = s[3];
            float4* o = (float4*)Hd + 4 * (size_t)i;
            o[0] = make_float4(f2tff(a.x), f2tff(b.x), f2tff(c.x), f2tff(d.x));
            o[1] = make_float4(f2tff(a.y), f2tff(b.y), f2tff(c.y), f2tff(d.y));
            o[2] = make_float4(f2tff(a.z), f2tff(b.z), f2tff(c.z), f2tff(d.z));
            o[3] = make_float4(f2tff(a.w), f2tff(b.w), f2tff(c.w), f2tff(d.w));
        }
    } else {
        float* dst = (z == 1) ? Wqd : (z == 2) ? Wkd : Wvd;
        const float* src = (z == 1) ? Wqs : (z == 2) ? Wks : Wvs;
        const int n4 = (int)(((z == 1) ? (size_t)DD * DD : (size_t)DD * KVD) / 4);
        for (; i < n4; i += stride) {
            float4 v = ((const float4*)src)[i];
            ((float4*)dst)[i] = make_float4(f2tff(v.x), f2tff(v.y), f2tff(v.z), f2tff(v.w));
        }
    }
}

// ---------------------------------------------------------------------------
// Transpose V[b][s][gd] -> Vt[b*512+gd][s], s 16-perm (launch #3).
// value at output position p (within 16-group) = 4*(p&3) + ((p>>2)&3).
// ---------------------------------------------------------------------------
__global__ void transpose_v(float* __restrict__ Vt, const float* __restrict__ V)
{
    __shared__ float t[32][33];
    const int s0 = blockIdx.x * 32, gd0 = blockIdx.y * 32, b = blockIdx.z;
    #pragma unroll
    for (int i = 0; i < 4; i++) {
        int row = threadIdx.y + i * 8;
        t[row][threadIdx.x] =
            V[((size_t)b * SS + s0 + row) * KVD + gd0 + threadIdx.x];
    }
    __syncthreads();
    const int j = threadIdx.x;
    const int ssrc = (j & 16) + 4 * (j & 3) + ((j >> 2) & 3);
    #pragma unroll
    for (int i = 0; i < 4; i++) {
        int gdl = threadIdx.y + i * 8;
        Vt[((size_t)b * KVD + gd0 + gdl) * SS + s0 + j] = t[ssrc][gdl];
    }
}

// ---------------------------------------------------------------------------
// Fused tf32 GEMM + bias (launch #2): z=0: Q (N=2048, scaled, 16-perm out),
// z=1: K (N=512, 16-perm out), z=2: V (N=512, plain out).
// CTA tile 128x256x32, 8 warps (2m x 4n), cp.async double-buffered.
// As[m][k] stride 48 (uint4 a-frag pairs, conflict-free); Bs[k][n] stride 264.
// ---------------------------------------------------------------------------
#define GA 6144
#define GB 8448
#define GBUF (GA + GB)
#define GEMM_SMEM_BYTES (GBUF * 2 * 4)

__device__ __forceinline__ void gemm_stage(
    unsigned sA, unsigned sB, const float* __restrict__ X, const float* __restrict__ W,
    int Kdim, int N, int bm, int bn, int k0, int tid)
{
    #pragma unroll
    for (int it = 0; it < 4; it++) {              // A: 128 x 32
        int f = tid + it * 256;
        int m  = f >> 3;
        int kq = (f & 7) * 4;
        CP16(sA + (m * 48 + kq) * 4, X + (size_t)(bm + m) * Kdim + k0 + kq);
    }
    #pragma unroll
    for (int it = 0; it < 8; it++) {              // B: 32 x 256
        int f = tid + it * 256;
        int kk = f >> 6;
        int nq = (f & 63) * 4;
        CP16(sB + (kk * 264 + nq) * 4, W + (size_t)(k0 + kk) * N + bn + nq);
    }
}

__global__ __launch_bounds__(256) void gemm_tf32(
    const float* __restrict__ X,
    const float* __restrict__ Wq, const float* __restrict__ bq, float* __restrict__ Yq,
    const float* __restrict__ Wk, const float* __restrict__ bk, float* __restrict__ Yk,
    const float* __restrict__ Wv, const float* __restrict__ bv, float* __restrict__ Yv,
    float qscale)
{
    const int z = blockIdx.z;
    if (z != 0 && blockIdx.x >= 2) return;        // KV: N=512 -> 2 col-tiles
    const float* __restrict__ W  = (z == 0) ? Wq : (z == 1) ? Wk : Wv;
    const float* __restrict__ bi = (z == 0) ? bq : (z == 1) ? bk : bv;
    float*       __restrict__ Y  = (z == 0) ? Yq : (z == 1) ? Yk : Yv;
    const int   N      = (z == 0) ? DD : KVD;
    const float oscale = (z == 0) ? qscale : 1.0f;
    const int   permv  = (z == 2) ? 0 : 1;

    extern __shared__ unsigned smg[];
    const int tid  = threadIdx.x;
    const int lane = tid & 31;
    const int wid  = tid >> 5;
    const int wm   = wid >> 2;     // 0..1
    const int wn   = wid & 3;      // 0..3
    const int lr   = lane >> 2;
    const int lc   = lane & 3;
    const int bm = blockIdx.y * 128;
    const int bn = blockIdx.x * 256;

    unsigned sbase = (unsigned)__cvta_generic_to_shared(smg);

    float acc[4][8][4];
    #pragma unroll
    for (int i = 0; i < 4; i++)
        #pragma unroll
        for (int j = 0; j < 8; j++)
            #pragma unroll
            for (int k = 0; k < 4; k++) acc[i][j][k] = 0.f;

    const int nK = DD / 32;
    gemm_stage(sbase, sbase + GA * 4, X, W, DD, N, bm, bn, 0, tid);
    CPCOMMIT();

    for (int i = 0; i < nK; i++) {
        CPWAIT(0);
        __syncthreads();
        if (i + 1 < nK) {
            unsigned boff = ((i + 1) & 1) * GBUF * 4;
            gemm_stage(sbase + boff, sbase + boff + GA * 4,
                       X, W, DD, N, bm, bn, (i + 1) * 32, tid);
            CPCOMMIT();
        }
        const unsigned* As = smg + (i & 1) * GBUF;
        const unsigned* Bs = As + GA;

        #pragma unroll
        for (int g = 0; g < 2; g++) {
            uint4 au[4][2];
            #pragma unroll
            for (int mt = 0; mt < 4; mt++) {
                int r = wm * 64 + mt * 16 + lr;
                au[mt][0] = *(const uint4*)&As[r * 48 + 16 * g + 4 * lc];
                au[mt][1] = *(const uint4*)&As[(r + 8) * 48 + 16 * g + 4 * lc];
            }
            #pragma unroll
            for (int hh = 0; hh < 2; hh++) {
                const int s = 2 * g + hh;
                const int c = s * 8 + lc;
                unsigned af[4][4], bf[8][2];
                #pragma unroll
                for (int mt = 0; mt < 4; mt++) {
                    if (hh == 0) {
                        af[mt][0] = au[mt][0].x; af[mt][1] = au[mt][1].x;
                        af[mt][2] = au[mt][0].y; af[mt][3] = au[mt][1].y;
                    } else {
                        af[mt][0] = au[mt][0].z; af[mt][1] = au[mt][1].z;
                        af[mt][2] = au[mt][0].w; af[mt][3] = au[mt][1].w;
                    }
                }
                #pragma unroll
                for (int nt = 0; nt < 8; nt++) {
                    int n = wn * 64 + nt * 8 + lr;
                    bf[nt][0] = Bs[c * 264 + n];
                    bf[nt][1] = Bs[(c + 4) * 264 + n];
                }
                #pragma unroll
                for (int mt = 0; mt < 4; mt++)
                    #pragma unroll
                    for (int nt = 0; nt < 8; nt++)
                        mma_tf32(acc[mt][nt], af[mt], bf[nt]);
            }
        }
        __syncthreads();
    }

    #pragma unroll
    for (int mt = 0; mt < 4; mt++) {
        int r = bm + wm * 64 + mt * 16 + lr;
        #pragma unroll
        for (int nt = 0; nt < 8; nt++) {
            int base = bn + wn * 64 + nt * 8;
            int c0 = base + 2 * lc, c1 = c0 + 1;
            float bv0 = bi[c0], bv1 = bi[c1];
            float v00 = f2tff((acc[mt][nt][0] + bv0) * oscale);
            float v01 = f2tff((acc[mt][nt][1] + bv1) * oscale);
            float v10 = f2tff((acc[mt][nt][2] + bv0) * oscale);
            float v11 = f2tff((acc[mt][nt][3] + bv1) * oscale);
            if (permv) {
                int p0 = (c0 & ~15) + 4 * (c0 & 3) + ((c0 >> 2) & 3);
                int p1 = (c1 & ~15) + 4 * (c1 & 3) + ((c1 >> 2) & 3);
                Y[(size_t)r * N + p0] = v00;
                Y[(size_t)r * N + p1] = v01;
                Y[(size_t)(r + 8) * N + p0] = v10;
                Y[(size_t)(r + 8) * N + p1] = v11;
            } else {
                *(float2*)(Y + (size_t)r * N + c0) = make_float2(v00, v01);
                *(float2*)(Y + (size_t)(r + 8) * N + c0) = make_float2(v10, v11);
            }
        }
    }
}

// ---------------------------------------------------------------------------
// tf32 flash attention (launch #4). Q register-resident; K triple-buffered
// (distance-2 prefetch), Vt double-buffered (distance-1); LDS.128 fragment
// loads via 16-perm (one uint4 = b-frags for two k-octets).
// SMEM floats: K 3x(64x144)=27648 | Vt 2x(128x80)=20480 | 10 mbarriers.
// ---------------------------------------------------------------------------
#define KSLOT 9216
#define VSLOT 10240
#define VBASE 27648
#define BARS  48128
#define ATTN_SMEM_BYTES (48160 * 4)

__global__ __launch_bounds__(256) void attn_tf32(
    const float* __restrict__ Q, const float* __restrict__ K,
    const float* __restrict__ Vt, float* __restrict__ O)
{
    extern __shared__ float sm[];

    const int tid  = threadIdx.x;
    const int lane = tid & 31;
    const int wid  = tid >> 5;
    const int lr = lane >> 2;
    const int lc = lane & 3;
    const int r0 = 16 * wid + lr;
    const int q0 = blockIdx.x * 128;
    const int h  = blockIdx.y;
    const int b  = blockIdx.z;
    const int g  = h & (HKV - 1);

    const float* Qb = Q  + (size_t)b * SS * DD  + (size_t)h * HD;
    const float* Kb = K  + (size_t)b * SS * KVD + (size_t)g * HD;
    const float* Vb = Vt + ((size_t)b * KVD + (size_t)g * HD) * SS;

    unsigned sbase = (unsigned)__cvta_generic_to_shared(sm);
    // barrier addresses (floats offsets): Kfull s: BARS+2s; Kempty: BARS+6+2s;
    // Vfull s: BARS+12+2s; Vempty: BARS+16+2s.

    if (tid == 0) {
        #pragma unroll
        for (int s = 0; s < 3; s++) {
            MBAR_INIT(sbase + (BARS + 2 * s) * 4, 256);
            MBAR_INIT(sbase + (BARS + 6 + 2 * s) * 4, 256);
        }
        #pragma unroll
        for (int s = 0; s < 2; s++) {
            MBAR_INIT(sbase + (BARS + 12 + 2 * s) * 4, 256);
            MBAR_INIT(sbase + (BARS + 16 + 2 * s) * 4, 256);
        }
    }

    // --- Prologue: stage Q through K region (stride 144), move to registers ---
    #pragma unroll
    for (int it = 0; it < 16; it++) {
        int f = tid + it * 256;
        int q  = f >> 5;
        int dq = (f & 31) * 4;
        CP16(sbase + (q * 144 + dq) * 4, Qb + (size_t)(q0 + q) * DD + dq);
    }
    CPCOMMIT();
    CPWAIT(0);
    __syncthreads();            // Q staged + barriers initialized

    unsigned qa[16][4];
    {
        const unsigned* Qs = (const unsigned*)sm;
        #pragma unroll
        for (int st2 = 0; st2 < 8; st2++) {
            uint4 u1 = *(const uint4*)&Qs[r0 * 144 + 16 * st2 + 4 * lc];
            uint4 u2 = *(const uint4*)&Qs[(r0 + 8) * 144 + 16 * st2 + 4 * lc];
            qa[2 * st2][0]     = u1.x; qa[2 * st2][1]     = u2.x;
            qa[2 * st2][2]     = u1.y; qa[2 * st2][3]     = u2.y;
            qa[2 * st2 + 1][0] = u1.z; qa[2 * st2 + 1][1] = u2.z;
            qa[2 * st2 + 1][2] = u1.w; qa[2 * st2 + 1][3] = u2.w;
        }
    }
    __syncthreads();            // all Q reads done before K slot fills

    // --- Fill K slots 0,1 and V slot 0 ---
    #pragma unroll
    for (int s = 0; s < 2; s++) {
        unsigned sKs = sbase + s * KSLOT * 4;
        #pragma unroll
        for (int it = 0; it < 8; it++) {
            int f = tid + it * 256;
            int key = f >> 5;
            int dq  = (f & 31) * 4;
            CP16(sKs + (key * 144 + dq) * 4,
                 Kb + (size_t)(s * 64 + key) * KVD + dq);
        }
        CPASYNC_MBAR_ARRIVE(sbase + (BARS + 2 * s) * 4);
    }
    {
        unsigned sVs = sbase + VBASE * 4;
        #pragma unroll
        for (int it = 0; it < 8; it++) {
            int f = tid + it * 256;
            int d  = f >> 4;
            int sq = (f & 15) * 4;
            CP16(sVs + (d * 80 + sq) * 4, Vb + (size_t)d * SS + sq);
        }
        CPASYNC_MBAR_ARRIVE(sbase + (BARS + 12) * 4);
    }

    float o[16][4];
    #pragma unroll
    for (int dt = 0; dt < 16; dt++)
        #pragma unroll
        for (int k = 0; k < 4; k++) o[dt][k] = 0.f;
    float rm0 = -INFINITY, rm1 = -INFINITY, rl0 = 0.f, rl1 = 0.f;

    const int sAsrc = lr * 4 + (lc >> 1);
    const int sBsrc = sAsrc + 2;
    const bool oddc = (lc & 1);

    #pragma unroll 1
    for (int kt = 0; kt < NT; kt++) {
        // --- producer: K(kt+2) ---
        const int fsk = kt + 2;
        if (fsk < NT) {
            const int ks = fsk % 3;
            if (fsk >= 3) MBAR_WAIT(sbase + (BARS + 6 + 2 * ks) * 4,
                                    (unsigned)(((fsk / 3) - 1) & 1));
            unsigned sKs = sbase + ks * KSLOT * 4;
            #pragma unroll
            for (int it = 0; it < 8; it++) {
                int f = tid + it * 256;
                int key = f >> 5;
                int dq  = (f & 31) * 4;
                CP16(sKs + (key * 144 + dq) * 4,
                     Kb + (size_t)(fsk * 64 + key) * KVD + dq);
            }
            CPASYNC_MBAR_ARRIVE(sbase + (BARS + 2 * ks) * 4);
        }
        // --- producer: V(kt+1) ---
        const int fsv = kt + 1;
        if (fsv < NT) {
            const int vs = fsv % 2;
            if (fsv >= 2) MBAR_WAIT(sbase + (BARS + 16 + 2 * vs) * 4,
                                    (unsigned)(((fsv / 2) - 1) & 1));
            unsigned sVs = sbase + (VBASE + vs * VSLOT) * 4;
            #pragma unroll
            for (int it = 0; it < 8; it++) {
                int f = tid + it * 256;
                int d  = f >> 4;
                int sq = (f & 15) * 4;
                CP16(sVs + (d * 80 + sq) * 4, Vb + (size_t)d * SS + fsv * 64 + sq);
            }
            CPASYNC_MBAR_ARRIVE(sbase + (BARS + 12 + 2 * vs) * 4);
        }

        // --- consumer: S = Q K^T ---
        const int kslot = kt % 3;
        MBAR_WAIT(sbase + (BARS + 2 * kslot) * 4, (unsigned)((kt / 3) & 1));
        const unsigned* Kst = (const unsigned*)(sm + kslot * KSLOT);

        float sacc[8][4];
        #pragma unroll
        for (int nt = 0; nt < 8; nt++)
            #pragma unroll
            for (int k = 0; k < 4; k++) sacc[nt][k] = 0.f;

        #pragma unroll
        for (int st2 = 0; st2 < 8; st2++) {
            #pragma unroll
            for (int nt = 0; nt < 8; nt++) {
                uint4 bu = *(const uint4*)&Kst[(8 * nt + lr) * 144 + 16 * st2 + 4 * lc];
                unsigned b0[2] = { bu.x, bu.y };
                unsigned b1[2] = { bu.z, bu.w };
                mma_tf32(sacc[nt], qa[2 * st2], b0);
                mma_tf32(sacc[nt], qa[2 * st2 + 1], b1);
            }
        }
        MBAR_ARRIVE(sbase + (BARS + 6 + 2 * kslot) * 4);   // release K early

        // --- warp-private online softmax; P -> a-frags via shuffles ---
        float m0 = sacc[0][0], m1 = sacc[0][2];
        #pragma unroll
        for (int nt = 0; nt < 8; nt++) {
            m0 = fmaxf(m0, fmaxf(sacc[nt][0], sacc[nt][1]));
            m1 = fmaxf(m1, fmaxf(sacc[nt][2], sacc[nt][3]));
        }
        m0 = fmaxf(m0, __shfl_xor_sync(0xffffffffu, m0, 1));
        m0 = fmaxf(m0, __shfl_xor_sync(0xffffffffu, m0, 2));
        m1 = fmaxf(m1, __shfl_xor_sync(0xffffffffu, m1, 1));
        m1 = fmaxf(m1, __shfl_xor_sync(0xffffffffu, m1, 2));
        float mn0 = fmaxf(rm0, m0), mn1 = fmaxf(rm1, m1);
        float al0 = __expf(rm0 - mn0), al1 = __expf(rm1 - mn1);
        float sum0 = 0.f, sum1 = 0.f;
        unsigned pa[8][4];
        #pragma unroll
        for (int nt = 0; nt < 8; nt++) {
            float f0 = __expf(sacc[nt][0] - mn0);
            float f1 = __expf(sacc[nt][1] - mn0);
            float f2 = __expf(sacc[nt][2] - mn1);
            float f3 = __expf(sacc[nt][3] - mn1);
            sum0 += f0 + f1;
            sum1 += f2 + f3;
            unsigned t0 = f2tf(f0), t1 = f2tf(f1), t2 = f2tf(f2), t3 = f2tf(f3);
            unsigned e0 = __shfl_sync(0xffffffffu, t0, sAsrc);
            unsigned o0 = __shfl_sync(0xffffffffu, t1, sAsrc);
            unsigned e1 = __shfl_sync(0xffffffffu, t2, sAsrc);
            unsigned o1 = __shfl_sync(0xffffffffu, t3, sAsrc);
            unsigned e2 = __shfl_sync(0xffffffffu, t0, sBsrc);
            unsigned o2 = __shfl_sync(0xffffffffu, t1, sBsrc);
            unsigned e3 = __shfl_sync(0xffffffffu, t2, sBsrc);
            unsigned o3 = __shfl_sync(0xffffffffu, t3, sBsrc);
            pa[nt][0] = oddc ? o0 : e0;
            pa[nt][1] = oddc ? o1 : e1;
            pa[nt][2] = oddc ? o2 : e2;
            pa[nt][3] = oddc ? o3 : e3;
        }
        sum0 += __shfl_xor_sync(0xffffffffu, sum0, 1);
        sum0 += __shfl_xor_sync(0xffffffffu, sum0, 2);
        sum1 += __shfl_xor_sync(0xffffffffu, sum1, 1);
        sum1 += __shfl_xor_sync(0xffffffffu, sum1, 2);
        rl0 = rl0 * al0 + sum0;  rm0 = mn0;
        rl1 = rl1 * al1 + sum1;  rm1 = mn1;
        #pragma unroll
        for (int dt = 0; dt < 16; dt++) {
            o[dt][0] *= al0;  o[dt][1] *= al0;
            o[dt][2] *= al1;  o[dt][3] *= al1;
        }

        // --- O += P V ---
        const int vslot = kt % 2;
        MBAR_WAIT(sbase + (BARS + 12 + 2 * vslot) * 4, (unsigned)((kt / 2) & 1));
        const unsigned* Vts = (const unsigned*)(sm + VBASE + vslot * VSLOT);
        #pragma unroll
        for (int nt2 = 0; nt2 < 4; nt2++) {
            #pragma unroll
            for (int dt = 0; dt < 16; dt++) {
                uint4 vu = *(const uint4*)&Vts[(8 * dt + lr) * 80 + 16 * nt2 + 4 * lc];
                unsigned b0[2] = { vu.x, vu.y };
                unsigned b1[2] = { vu.z, vu.w };
                mma_tf32(o[dt], pa[2 * nt2], b0);
                mma_tf32(o[dt], pa[2 * nt2 + 1], b1);
            }
        }
        MBAR_ARRIVE(sbase + (BARS + 16 + 2 * vslot) * 4);
    }

    // Epilogue
    float* Ob = O + (size_t)b * SS * DD + (size_t)h * HD;
    float inv0 = 1.f / rl0, inv1 = 1.f / rl1;
    #pragma unroll
    for (int dt = 0; dt < 16; dt++) {
        int cc = 8 * dt + 2 * lc;
        *(float2*)(Ob + (size_t)(q0 + r0) * DD + cc) =
            make_float2(o[dt][0] * inv0, o[dt][1] * inv0);
        *(float2*)(Ob + (size_t)(q0 + r0 + 8) * DD + cc) =
            make_float2(o[dt][2] * inv1, o[dt][3] * inv1);
    }
}

// ---------------------------------------------------------------------------
extern "C" void kernel_launch(void* const* d_in, const int* in_sizes, int n_in,
                              void* d_out, int out_size)
{
    (void)in_sizes; (void)n_in; (void)out_size;
    const float* H  = (const float*)d_in[0];
    const float* Wq = (const float*)d_in[1];
    const float* bq = (const float*)d_in[2];
    const float* Wk = (const float*)d_in[3];
    const float* bk = (const float*)d_in[4];
    const float* Wv = (const float*)d_in[5];
    const float* bv = (const float*)d_in[6];
    float* out = (float*)d_out;

    float *Qp, *Kp, *Vp, *Vtp, *Hp, *Wqp, *Wkp, *Wvp;
    cudaGetSymbolAddress((void**)&Qp,  g_Q);
    cudaGetSymbolAddress((void**)&Kp,  g_K);
    cudaGetSymbolAddress((void**)&Vp,  g_V);
    cudaGetSymbolAddress((void**)&Vtp, g_Vt);
    cudaGetSymbolAddress((void**)&Hp,  g_H);
    cudaGetSymbolAddress((void**)&Wqp, g_Wq);
    cudaGetSymbolAddress((void**)&Wkp, g_Wk);
    cudaGetSymbolAddress((void**)&Wvp, g_Wv);

    cudaFuncSetAttribute(gemm_tf32,
                         cudaFuncAttributeMaxDynamicSharedMemorySize, GEMM_SMEM_BYTES);
    cudaFuncSetAttribute(attn_tf32,
                         cudaFuncAttributeMaxDynamicSharedMemorySize, ATTN_SMEM_BYTES);

    const float scale = 0.08838834764831845f;  // 1/sqrt(128)

    // #1: fused pre-pass (H 16-perm + 3 weights)
    cvt_fused<<<dim3(296, 1, 4), 256>>>(Hp, H, Wqp, Wq, Wkp, Wk, Wvp, Wv);
    // #2: fused Q/K/V projections
    gemm_tf32<<<dim3(DD / 256, MM / 128, 3), 256, GEMM_SMEM_BYTES>>>(
        Hp, Wqp, bq, Qp, Wkp, bk, Kp, Wvp, bv, Vp, scale);
    // #3: V transpose (s 16-perm)
    transpose_v<<<dim3(SS / 32, KVD / 32, BB), dim3(32, 8)>>>(Vtp, Vp);
    // #4: attention (profiled launch)
    attn_tf32<<<dim3(SS / 128, HQ, BB), 256, ATTN_SMEM_BYTES>>>(Qp, Kp, Vtp, out);
}

// round 11
// speedup vs baseline: 1.0029x; 1.0029x over previous
#include <cuda_runtime.h>
#include <math.h>

#define BB   2
#define SS   2048
#define DD   2048
#define HQ   16
#define HKV  4
#define HD   128
#define KVD  512
#define MM   (BB*SS)
#define NT   (SS/64)

// Scratch (device globals)
__device__ float g_Q[(size_t)MM * DD];    // [token][d]  d 16-perm, scaled
__device__ float g_K[(size_t)MM * KVD];   // [token][gd] d 16-perm
__device__ float g_V[(size_t)MM * KVD];   // [token][gd] plain
__device__ float g_Vt[(size_t)BB * KVD * SS]; // [b*512+gd][s] s 16-perm
__device__ float g_H[(size_t)MM * DD];    // tf32-rounded, k 16-perm
__device__ float g_Wq[(size_t)DD * DD];   // [k][n] tf32-rounded
__device__ float g_Wk[(size_t)DD * KVD];
__device__ float g_Wv[(size_t)DD * KVD];

__device__ __forceinline__ unsigned f2tf(float x) {
    unsigned r;
    asm("cvt.rna.tf32.f32 %0, %1;" : "=r"(r) : "f"(x));
    return r;
}
__device__ __forceinline__ float f2tff(float x) { return __uint_as_float(f2tf(x)); }

__device__ __forceinline__ void mma_tf32(float c[4], const unsigned a[4], const unsigned b[2]) {
    asm volatile(
        "mma.sync.aligned.m16n8k8.row.col.f32.tf32.tf32.f32 "
        "{%0,%1,%2,%3},{%4,%5,%6,%7},{%8,%9},{%0,%1,%2,%3};"
        : "+f"(c[0]), "+f"(c[1]), "+f"(c[2]), "+f"(c[3])
        : "r"(a[0]), "r"(a[1]), "r"(a[2]), "r"(a[3]), "r"(b[0]), "r"(b[1]));
}

#define CP16(dst, src) \
    asm volatile("cp.async.cg.shared.global [%0], [%1], 16;" :: "r"(dst), "l"(src))
#define CPCOMMIT() asm volatile("cp.async.commit_group;")
#define CPWAIT(N)  asm volatile("cp.async.wait_group %0;" :: "n"(N))

#define MBAR_INIT(addr, cnt) \
    asm volatile("mbarrier.init.shared.b64 [%0], %1;" :: "r"(addr), "r"(cnt) : "memory")
#define MBAR_ARRIVE(addr) \
    asm volatile("mbarrier.arrive.shared.b64 _, [%0];" :: "r"(addr) : "memory")
#define CPASYNC_MBAR_ARRIVE(addr) \
    asm volatile("cp.async.mbarrier.arrive.noinc.shared.b64 [%0];" :: "r"(addr) : "memory")

#define MBAR_WAIT(addr, par) do { \
    unsigned _m = (addr), _p = (par), _d; \
    asm volatile("{\n\t.reg .pred p;\n\t" \
        "mbarrier.try_wait.parity.acquire.cta.shared::cta.b64 p, [%1], %2;\n\t" \
        "selp.b32 %0, 1, 0, p;\n\t}" : "=r"(_d) : "r"(_m), "r"(_p) : "memory"); \
    if (!_d) { \
        asm volatile("{\n\t.reg .pred P1;\n\t" \
            "WL%=:\n\t" \
            "mbarrier.try_wait.parity.acquire.cta.shared::cta.b64 P1, [%0], %1, 0x989680;\n\t" \
            "@P1 bra.uni WD%=;\n\t" \
            "bra.uni WL%=;\n\t" \
            "WD%=:\n\t}" :: "r"(_m), "r"(_p) : "memory"); \
    } \
} while (0)

// ---------------------------------------------------------------------------
// tf32-round, natural order (weights)
// ---------------------------------------------------------------------------
__global__ void cvt_tf32(float* __restrict__ dst, const float* __restrict__ src, int n4)
{
    int i = blockIdx.x * blockDim.x + threadIdx.x;
    int stride = gridDim.x * blockDim.x;
    for (; i < n4; i += stride) {
        float4 v = ((const float4*)src)[i];
        ((float4*)dst)[i] = make_float4(f2tff(v.x), f2tff(v.y), f2tff(v.z), f2tff(v.w));
    }
}

// ---------------------------------------------------------------------------
// tf32-round + 16-wide perm (4x4 transpose per 16-group)  (H / activations)
// ---------------------------------------------------------------------------
__global__ void cvt_tf32_p16(float* __restrict__ dst, const float* __restrict__ src, int n16)
{
    int i = blockIdx.x * blockDim.x + threadIdx.x;
    int stride = gridDim.x * blockDim.x;
    for (; i < n16; i += stride) {
        const float4* s = (const float4*)src + 4 * (size_t)i;
        float4 a = s[0], b = s[1], c = s[2], d = s[3];
        float4* o = (float4*)dst + 4 * (size_t)i;
        o[0] = make_float4(f2tff(a.x), f2tff(b.x), f2tff(c.x), f2tff(d.x));
        o[1] = make_float4(f2tff(a.y), f2tff(b.y), f2tff(c.y), f2tff(d.y));
        o[2] = make_float4(f2tff(a.z), f2tff(b.z), f2tff(c.z), f2tff(d.z));
        o[3] = make_float4(f2tff(a.w), f2tff(b.w), f2tff(c.w), f2tff(d.w));
    }
}

// ---------------------------------------------------------------------------
// Transpose V[b][s][gd] -> Vt[b*512+gd][s], s 16-perm.
// ---------------------------------------------------------------------------
__global__ void transpose_v(float* __restrict__ Vt, const float* __restrict__ V)
{
    __shared__ float t[32][33];
    const int s0 = blockIdx.x * 32, gd0 = blockIdx.y * 32, b = blockIdx.z;
    #pragma unroll
    for (int i = 0; i < 4; i++) {
        int row = threadIdx.y + i * 8;
        t[row][threadIdx.x] =
            V[((size_t)b * SS + s0 + row) * KVD + gd0 + threadIdx.x];
    }
    __syncthreads();
    const int j = threadIdx.x;
    const int ssrc = (j & 16) + 4 * (j & 3) + ((j >> 2) & 3);
    #pragma unroll
    for (int i = 0; i < 4; i++) {
        int gdl = threadIdx.y + i * 8;
        Vt[((size_t)b * KVD + gd0 + gdl) * SS + s0 + j] = t[ssrc][gdl];
    }
}

// ---------------------------------------------------------------------------
// tf32 GEMM + bias. z = blockIdx.z + zoff: 0=Q (N=2048, scaled, 16-perm out),
// 1=K (N=512, 16-perm out), 2=V (N=512, plain out). Exact grids per launch.
// CTA tile 128x256x32, 8 warps, cp.async double-buffered.
// As[m][k] stride 48 (uint4 a-frag pairs); Bs[k][n] stride 264.
// ---------------------------------------------------------------------------
#define GA 6144
#define GB 8448
#define GBUF (GA + GB)
#define GEMM_SMEM_BYTES (GBUF * 2 * 4)

__device__ __forceinline__ void gemm_stage(
    unsigned sA, unsigned sB, const float* __restrict__ X, const float* __restrict__ W,
    int N, int bm, int bn, int k0, int tid)
{
    #pragma unroll
    for (int it = 0; it < 4; it++) {              // A: 128 x 32
        int f = tid + it * 256;
        int m  = f >> 3;
        int kq = (f & 7) * 4;
        CP16(sA + (m * 48 + kq) * 4, X + (size_t)(bm + m) * DD + k0 + kq);
    }
    #pragma unroll
    for (int it = 0; it < 8; it++) {              // B: 32 x 256
        int f = tid + it * 256;
        int kk = f >> 6;
        int nq = (f & 63) * 4;
        CP16(sB + (kk * 264 + nq) * 4, W + (size_t)(k0 + kk) * N + bn + nq);
    }
}

__global__ __launch_bounds__(256) void gemm_tf32(
    const float* __restrict__ X,
    const float* __restrict__ Wq, const float* __restrict__ bq, float* __restrict__ Yq,
    const float* __restrict__ Wk, const float* __restrict__ bk, float* __restrict__ Yk,
    const float* __restrict__ Wv, const float* __restrict__ bv, float* __restrict__ Yv,
    float qscale, int zoff)
{
    const int z = blockIdx.z + zoff;
    const float* __restrict__ W  = (z == 0) ? Wq : (z == 1) ? Wk : Wv;
    const float* __restrict__ bi = (z == 0) ? bq : (z == 1) ? bk : bv;
    float*       __restrict__ Y  = (z == 0) ? Yq : (z == 1) ? Yk : Yv;
    const int   N      = (z == 0) ? DD : KVD;
    const float oscale = (z == 0) ? qscale : 1.0f;
    const int   permv  = (z == 2) ? 0 : 1;

    extern __shared__ unsigned smg[];
    const int tid  = threadIdx.x;
    const int lane = tid & 31;
    const int wid  = tid >> 5;
    const int wm   = wid >> 2;
    const int wn   = wid & 3;
    const int lr   = lane >> 2;
    const int lc   = lane & 3;
    const int bm = blockIdx.y * 128;
    const int bn = blockIdx.x * 256;

    unsigned sbase = (unsigned)__cvta_generic_to_shared(smg);

    float acc[4][8][4];
    #pragma unroll
    for (int i = 0; i < 4; i++)
        #pragma unroll
        for (int j = 0; j < 8; j++)
            #pragma unroll
            for (int k = 0; k < 4; k++) acc[i][j][k] = 0.f;

    const int nK = DD / 32;
    gemm_stage(sbase, sbase + GA * 4, X, W, N, bm, bn, 0, tid);
    CPCOMMIT();

    for (int i = 0; i < nK; i++) {
        CPWAIT(0);
        __syncthreads();
        if (i + 1 < nK) {
            unsigned boff = ((i + 1) & 1) * GBUF * 4;
            gemm_stage(sbase + boff, sbase + boff + GA * 4,
                       X, W, N, bm, bn, (i + 1) * 32, tid);
            CPCOMMIT();
        }
        const unsigned* As = smg + (i & 1) * GBUF;
        const unsigned* Bs = As + GA;

        #pragma unroll
        for (int g = 0; g < 2; g++) {
            uint4 au[4][2];
            #pragma unroll
            for (int mt = 0; mt < 4; mt++) {
                int r = wm * 64 + mt * 16 + lr;
                au[mt][0] = *(const uint4*)&As[r * 48 + 16 * g + 4 * lc];
                au[mt][1] = *(const uint4*)&As[(r + 8) * 48 + 16 * g + 4 * lc];
            }
            #pragma unroll
            for (int hh = 0; hh < 2; hh++) {
                const int s = 2 * g + hh;
                const int c = s * 8 + lc;
                unsigned af[4][4], bf[8][2];
                #pragma unroll
                for (int mt = 0; mt < 4; mt++) {
                    if (hh == 0) {
                        af[mt][0] = au[mt][0].x; af[mt][1] = au[mt][1].x;
                        af[mt][2] = au[mt][0].y; af[mt][3] = au[mt][1].y;
                    } else {
                        af[mt][0] = au[mt][0].z; af[mt][1] = au[mt][1].z;
                        af[mt][2] = au[mt][0].w; af[mt][3] = au[mt][1].w;
                    }
                }
                #pragma unroll
                for (int nt = 0; nt < 8; nt++) {
                    int n = wn * 64 + nt * 8 + lr;
                    bf[nt][0] = Bs[c * 264 + n];
                    bf[nt][1] = Bs[(c + 4) * 264 + n];
                }
                #pragma unroll
                for (int mt = 0; mt < 4; mt++)
                    #pragma unroll
                    for (int nt = 0; nt < 8; nt++)
                        mma_tf32(acc[mt][nt], af[mt], bf[nt]);
            }
        }
        __syncthreads();
    }

    #pragma unroll
    for (int mt = 0; mt < 4; mt++) {
        int r = bm + wm * 64 + mt * 16 + lr;
        #pragma unroll
        for (int nt = 0; nt < 8; nt++) {
            int base = bn + wn * 64 + nt * 8;
            int c0 = base + 2 * lc, c1 = c0 + 1;
            float bv0 = bi[c0], bv1 = bi[c1];
            float v00 = f2tff((acc[mt][nt][0] + bv0) * oscale);
            float v01 = f2tff((acc[mt][nt][1] + bv1) * oscale);
            float v10 = f2tff((acc[mt][nt][2] + bv0) * oscale);
            float v11 = f2tff((acc[mt][nt][3] + bv1) * oscale);
            if (permv) {
                int p0 = (c0 & ~15) + 4 * (c0 & 3) + ((c0 >> 2) & 3);
                int p1 = (c1 & ~15) + 4 * (c1 & 3) + ((c1 >> 2) & 3);
                Y[(size_t)r * N + p0] = v00;
                Y[(size_t)r * N + p1] = v01;
                Y[(size_t)(r + 8) * N + p0] = v10;
                Y[(size_t)(r + 8) * N + p1] = v11;
            } else {
                *(float2*)(Y + (size_t)r * N + c0) = make_float2(v00, v01);
                *(float2*)(Y + (size_t)(r + 8) * N + c0) = make_float2(v10, v11);
            }
        }
    }
}

// ---------------------------------------------------------------------------
// tf32 flash attention — byte-identical to round 10's measured 497us kernel.
// ---------------------------------------------------------------------------
#define KSLOT 9216
#define VSLOT 10240
#define VBASE 27648
#define BARS  48128
#define ATTN_SMEM_BYTES (48160 * 4)

__global__ __launch_bounds__(256) void attn_tf32(
    const float* __restrict__ Q, const float* __restrict__ K,
    const float* __restrict__ Vt, float* __restrict__ O)
{
    extern __shared__ float sm[];

    const int tid  = threadIdx.x;
    const int lane = tid & 31;
    const int wid  = tid >> 5;
    const int lr = lane >> 2;
    const int lc = lane & 3;
    const int r0 = 16 * wid + lr;
    const int q0 = blockIdx.x * 128;
    const int h  = blockIdx.y;
    const int b  = blockIdx.z;
    const int g  = h & (HKV - 1);

    const float* Qb = Q  + (size_t)b * SS * DD  + (size_t)h * HD;
    const float* Kb = K  + (size_t)b * SS * KVD + (size_t)g * HD;
    const float* Vb = Vt + ((size_t)b * KVD + (size_t)g * HD) * SS;

    unsigned sbase = (unsigned)__cvta_generic_to_shared(sm);

    if (tid == 0) {
        #pragma unroll
        for (int s = 0; s < 3; s++) {
            MBAR_INIT(sbase + (BARS + 2 * s) * 4, 256);
            MBAR_INIT(sbase + (BARS + 6 + 2 * s) * 4, 256);
        }
        #pragma unroll
        for (int s = 0; s < 2; s++) {
            MBAR_INIT(sbase + (BARS + 12 + 2 * s) * 4, 256);
            MBAR_INIT(sbase + (BARS + 16 + 2 * s) * 4, 256);
        }
    }

    #pragma unroll
    for (int it = 0; it < 16; it++) {
        int f = tid + it * 256;
        int q  = f >> 5;
        int dq = (f & 31) * 4;
        CP16(sbase + (q * 144 + dq) * 4, Qb + (size_t)(q0 + q) * DD + dq);
    }
    CPCOMMIT();
    CPWAIT(0);
    __syncthreads();

    unsigned qa[16][4];
    {
        const unsigned* Qs = (const unsigned*)sm;
        #pragma unroll
        for (int st2 = 0; st2 < 8; st2++) {
            uint4 u1 = *(const uint4*)&Qs[r0 * 144 + 16 * st2 + 4 * lc];
            uint4 u2 = *(const uint4*)&Qs[(r0 + 8) * 144 + 16 * st2 + 4 * lc];
            qa[2 * st2][0]     = u1.x; qa[2 * st2][1]     = u2.x;
            qa[2 * st2][2]     = u1.y; qa[2 * st2][3]     = u2.y;
            qa[2 * st2 + 1][0] = u1.z; qa[2 * st2 + 1][1] = u2.z;
            qa[2 * st2 + 1][2] = u1.w; qa[2 * st2 + 1][3] = u2.w;
        }
    }
    __syncthreads();

    #pragma unroll
    for (int s = 0; s < 2; s++) {
        unsigned sKs = sbase + s * KSLOT * 4;
        #pragma unroll
        for (int it = 0; it < 8; it++) {
            int f = tid + it * 256;
            int key = f >> 5;
            int dq  = (f & 31) * 4;
            CP16(sKs + (key * 144 + dq) * 4,
                 Kb + (size_t)(s * 64 + key) * KVD + dq);
        }
        CPASYNC_MBAR_ARRIVE(sbase + (BARS + 2 * s) * 4);
    }
    {
        unsigned sVs = sbase + VBASE * 4;
        #pragma unroll
        for (int it = 0; it < 8; it++) {
            int f = tid + it * 256;
            int d  = f >> 4;
            int sq = (f & 15) * 4;
            CP16(sVs + (d * 80 + sq) * 4, Vb + (size_t)d * SS + sq);
        }
        CPASYNC_MBAR_ARRIVE(sbase + (BARS + 12) * 4);
    }

    float o[16][4];
    #pragma unroll
    for (int dt = 0; dt < 16; dt++)
        #pragma unroll
        for (int k = 0; k < 4; k++) o[dt][k] = 0.f;
    float rm0 = -INFINITY, rm1 = -INFINITY, rl0 = 0.f, rl1 = 0.f;

    const int sAsrc = lr * 4 + (lc >> 1);
    const int sBsrc = sAsrc + 2;
    const bool oddc = (lc & 1);

    #pragma unroll 1
    for (int kt = 0; kt < NT; kt++) {
        const int fsk = kt + 2;
        if (fsk < NT) {
            const int ks = fsk % 3;
            if (fsk >= 3) MBAR_WAIT(sbase + (BARS + 6 + 2 * ks) * 4,
                                    (unsigned)(((fsk / 3) - 1) & 1));
            unsigned sKs = sbase + ks * KSLOT * 4;
            #pragma unroll
            for (int it = 0; it < 8; it++) {
                int f = tid + it * 256;
                int key = f >> 5;
                int dq  = (f & 31) * 4;
                CP16(sKs + (key * 144 + dq) * 4,
                     Kb + (size_t)(fsk * 64 + key) * KVD + dq);
            }
            CPASYNC_MBAR_ARRIVE(sbase + (BARS + 2 * ks) * 4);
        }
        const int fsv = kt + 1;
        if (fsv < NT) {
            const int vs = fsv % 2;
            if (fsv >= 2) MBAR_WAIT(sbase + (BARS + 16 + 2 * vs) * 4,
                                    (unsigned)(((fsv / 2) - 1) & 1));
            unsigned sVs = sbase + (VBASE + vs * VSLOT) * 4;
            #pragma unroll
            for (int it = 0; it < 8; it++) {
                int f = tid + it * 256;
                int d  = f >> 4;
                int sq = (f & 15) * 4;
                CP16(sVs + (d * 80 + sq) * 4, Vb + (size_t)d * SS + fsv * 64 + sq);
            }
            CPASYNC_MBAR_ARRIVE(sbase + (BARS + 12 + 2 * vs) * 4);
        }

        const int kslot = kt % 3;
        MBAR_WAIT(sbase + (BARS + 2 * kslot) * 4, (unsigned)((kt / 3) & 1));
        const unsigned* Kst = (const unsigned*)(sm + kslot * KSLOT);

        float sacc[8][4];
        #pragma unroll
        for (int nt = 0; nt < 8; nt++)
            #pragma unroll
            for (int k = 0; k < 4; k++) sacc[nt][k] = 0.f;

        #pragma unroll
        for (int st2 = 0; st2 < 8; st2++) {
            #pragma unroll
            for (int nt = 0; nt < 8; nt++) {
                uint4 bu = *(const uint4*)&Kst[(8 * nt + lr) * 144 + 16 * st2 + 4 * lc];
                unsigned b0[2] = { bu.x, bu.y };
                unsigned b1[2] = { bu.z, bu.w };
                mma_tf32(sacc[nt], qa[2 * st2], b0);
                mma_tf32(sacc[nt], qa[2 * st2 + 1], b1);
            }
        }
        MBAR_ARRIVE(sbase + (BARS + 6 + 2 * kslot) * 4);

        float m0 = sacc[0][0], m1 = sacc[0][2];
        #pragma unroll
        for (int nt = 0; nt < 8; nt++) {
            m0 = fmaxf(m0, fmaxf(sacc[nt][0], sacc[nt][1]));
            m1 = fmaxf(m1, fmaxf(sacc[nt][2], sacc[nt][3]));
        }
        m0 = fmaxf(m0, __shfl_xor_sync(0xffffffffu, m0, 1));
        m0 = fmaxf(m0, __shfl_xor_sync(0xffffffffu, m0, 2));
        m1 = fmaxf(m1, __shfl_xor_sync(0xffffffffu, m1, 1));
        m1 = fmaxf(m1, __shfl_xor_sync(0xffffffffu, m1, 2));
        float mn0 = fmaxf(rm0, m0), mn1 = fmaxf(rm1, m1);
        float al0 = __expf(rm0 - mn0), al1 = __expf(rm1 - mn1);
        float sum0 = 0.f, sum1 = 0.f;
        unsigned pa[8][4];
        #pragma unroll
        for (int nt = 0; nt < 8; nt++) {
            float f0 = __expf(sacc[nt][0] - mn0);
            float f1 = __expf(sacc[nt][1] - mn0);
            float f2 = __expf(sacc[nt][2] - mn1);
            float f3 = __expf(sacc[nt][3] - mn1);
            sum0 += f0 + f1;
            sum1 += f2 + f3;
            unsigned t0 = f2tf(f0), t1 = f2tf(f1), t2 = f2tf(f2), t3 = f2tf(f3);
            unsigned e0 = __shfl_sync(0xffffffffu, t0, sAsrc);
            unsigned o0 = __shfl_sync(0xffffffffu, t1, sAsrc);
            unsigned e1 = __shfl_sync(0xffffffffu, t2, sAsrc);
            unsigned o1 = __shfl_sync(0xffffffffu, t3, sAsrc);
            unsigned e2 = __shfl_sync(0xffffffffu, t0, sBsrc);
            unsigned o2 = __shfl_sync(0xffffffffu, t1, sBsrc);
            unsigned e3 = __shfl_sync(0xffffffffu, t2, sBsrc);
            unsigned o3 = __shfl_sync(0xffffffffu, t3, sBsrc);
            pa[nt][0] = oddc ? o0 : e0;
            pa[nt][1] = oddc ? o1 : e1;
            pa[nt][2] = oddc ? o2 : e2;
            pa[nt][3] = oddc ? o3 : e3;
        }
        sum0 += __shfl_xor_sync(0xffffffffu, sum0, 1);
        sum0 += __shfl_xor_sync(0xffffffffu, sum0, 2);
        sum1 += __shfl_xor_sync(0xffffffffu, sum1, 1);
        sum1 += __shfl_xor_sync(0xffffffffu, sum1, 2);
        rl0 = rl0 * al0 + sum0;  rm0 = mn0;
        rl1 = rl1 * al1 + sum1;  rm1 = mn1;
        #pragma unroll
        for (int dt = 0; dt < 16; dt++) {
            o[dt][0] *= al0;  o[dt][1] *= al0;
            o[dt][2] *= al1;  o[dt][3] *= al1;
        }

        const int vslot = kt % 2;
        MBAR_WAIT(sbase + (BARS + 12 + 2 * vslot) * 4, (unsigned)((kt / 2) & 1));
        const unsigned* Vts = (const unsigned*)(sm + VBASE + vslot * VSLOT);
        #pragma unroll
        for (int nt2 = 0; nt2 < 4; nt2++) {
            #pragma unroll
            for (int dt = 0; dt < 16; dt++) {
                uint4 vu = *(const uint4*)&Vts[(8 * dt + lr) * 80 + 16 * nt2 + 4 * lc];
                unsigned b0[2] = { vu.x, vu.y };
                unsigned b1[2] = { vu.z, vu.w };
                mma_tf32(o[dt], pa[2 * nt2], b0);
                mma_tf32(o[dt], pa[2 * nt2 + 1], b1);
            }
        }
        MBAR_ARRIVE(sbase + (BARS + 16 + 2 * vslot) * 4);
    }

    float* Ob = O + (size_t)b * SS * DD + (size_t)h * HD;
    float inv0 = 1.f / rl0, inv1 = 1.f / rl1;
    #pragma unroll
    for (int dt = 0; dt < 16; dt++) {
        int cc = 8 * dt + 2 * lc;
        *(float2*)(Ob + (size_t)(q0 + r0) * DD + cc) =
            make_float2(o[dt][0] * inv0, o[dt][1] * inv0);
        *(float2*)(Ob + (size_t)(q0 + r0 + 8) * DD + cc) =
            make_float2(o[dt][2] * inv1, o[dt][3] * inv1);
    }
}

// ---------------------------------------------------------------------------
// Launch: two-stream fork/join (round-9 schedule, round-10 kernels).
// ---------------------------------------------------------------------------
extern "C" void kernel_launch(void* const* d_in, const int* in_sizes, int n_in,
                              void* d_out, int out_size)
{
    (void)in_sizes; (void)n_in; (void)out_size;
    const float* H  = (const float*)d_in[0];
    const float* Wq = (const float*)d_in[1];
    const float* bq = (const float*)d_in[2];
    const float* Wk = (const float*)d_in[3];
    const float* bk = (const float*)d_in[4];
    const float* Wv = (const float*)d_in[5];
    const float* bv = (const float*)d_in[6];
    float* out = (float*)d_out;

    static cudaStream_t s2 = 0;
    static cudaEvent_t eFork = 0, eH = 0, eKV = 0;
    if (s2 == 0) {
        cudaStreamCreateWithFlags(&s2, cudaStreamNonBlocking);
        cudaEventCreateWithFlags(&eFork, cudaEventDisableTiming);
        cudaEventCreateWithFlags(&eH,    cudaEventDisableTiming);
        cudaEventCreateWithFlags(&eKV,   cudaEventDisableTiming);
    }

    float *Qp, *Kp, *Vp, *Vtp, *Hp, *Wqp, *Wkp, *Wvp;
    cudaGetSymbolAddress((void**)&Qp,  g_Q);
    cudaGetSymbolAddress((void**)&Kp,  g_K);
    cudaGetSymbolAddress((void**)&Vp,  g_V);
    cudaGetSymbolAddress((void**)&Vtp, g_Vt);
    cudaGetSymbolAddress((void**)&Hp,  g_H);
    cudaGetSymbolAddress((void**)&Wqp, g_Wq);
    cudaGetSymbolAddress((void**)&Wkp, g_Wk);
    cudaGetSymbolAddress((void**)&Wvp, g_Wv);

    cudaFuncSetAttribute(gemm_tf32,
                         cudaFuncAttributeMaxDynamicSharedMemorySize, GEMM_SMEM_BYTES);
    cudaFuncSetAttribute(attn_tf32,
                         cudaFuncAttributeMaxDynamicSharedMemorySize, ATTN_SMEM_BYTES);

    const float scale = 0.08838834764831845f;  // 1/sqrt(128)
    const int nb = 148 * 8;

    // Fork s2 off the capture/main stream.
    cudaEventRecord(eFork, 0);
    cudaStreamWaitEvent(s2, eFork, 0);

    // Stream 0: H (16-perm) + Wq cvt.
    cvt_tf32_p16<<<nb, 256>>>(Hp, H, (int)((size_t)MM * DD / 16));
    cvt_tf32<<<nb, 256>>>(Wqp, Wq, (int)((size_t)DD * DD / 4));
    cudaEventRecord(eH, 0);

    // Stream s2: Wk/Wv cvt (independent of H), then wait for H.
    cvt_tf32<<<nb, 256, 0, s2>>>(Wkp, Wk, (int)((size_t)DD * KVD / 4));
    cvt_tf32<<<nb, 256, 0, s2>>>(Wvp, Wv, (int)((size_t)DD * KVD / 4));
    cudaStreamWaitEvent(s2, eH, 0);

    // Stream 0: Q projection (z=0 only, exact grid).
    gemm_tf32<<<dim3(DD / 256, MM / 128, 1), 256, GEMM_SMEM_BYTES>>>(
        Hp, Wqp, bq, Qp, Wkp, bk, Kp, Wvp, bv, Vp, scale, 0);

    // Stream s2: K + V projections (z=1,2, exact grid), then V transpose.
    gemm_tf32<<<dim3(KVD / 256, MM / 128, 2), 256, GEMM_SMEM_BYTES, s2>>>(
        Hp, Wqp, bq, Qp, Wkp, bk, Kp, Wvp, bv, Vp, scale, 1);
    transpose_v<<<dim3(SS / 32, KVD / 32, BB), dim3(32, 8), 0, s2>>>(Vtp, Vp);
    cudaEventRecord(eKV, s2);

    // Join: attention needs Q (stream 0) and K/Vt (s2).
    cudaStreamWaitEvent(0, eKV, 0);
    attn_tf32<<<dim3(SS / 128, HQ, BB), 256, ATTN_SMEM_BYTES>>>(Qp, Kp, Vtp, out);
}

// round 12
// speedup vs baseline: 1.1147x; 1.1115x over previous
#include <cuda_runtime.h>
#include <math.h>

#define BB   2
#define SS   2048
#define DD   2048
#define HQ   16
#define HKV  4
#define HD   128
#define KVD  512
#define MM   (BB*SS)
#define NT   (SS/64)

// Scratch (device globals)
__device__ float g_Q[(size_t)MM * DD];    // [token][d]  d-octets permuted, scaled
__device__ float g_K[(size_t)MM * KVD];   // [token][gd] d-octets permuted
__device__ float g_V[(size_t)MM * KVD];   // [token][gd] plain
__device__ float g_Vt[(size_t)BB * KVD * SS]; // [b*512+gd][s] s-octets permuted
__device__ float g_H[(size_t)MM * DD];    // tf32-rounded, k-octets permuted
__device__ float g_Wq[(size_t)DD * DD];   // [k][n] tf32-rounded
__device__ float g_Wk[(size_t)DD * KVD];
__device__ float g_Wv[(size_t)DD * KVD];

__device__ __forceinline__ unsigned f2tf(float x) {
    unsigned r;
    asm("cvt.rna.tf32.f32 %0, %1;" : "=r"(r) : "f"(x));
    return r;
}
__device__ __forceinline__ float f2tff(float x) { return __uint_as_float(f2tf(x)); }

__device__ __forceinline__ void mma_tf32(float c[4], const unsigned a[4], const unsigned b[2]) {
    asm volatile(
        "mma.sync.aligned.m16n8k8.row.col.f32.tf32.tf32.f32 "
        "{%0,%1,%2,%3},{%4,%5,%6,%7},{%8,%9},{%0,%1,%2,%3};"
        : "+f"(c[0]), "+f"(c[1]), "+f"(c[2]), "+f"(c[3])
        : "r"(a[0]), "r"(a[1]), "r"(a[2]), "r"(a[3]), "r"(b[0]), "r"(b[1]));
}

#define CP16(dst, src) \
    asm volatile("cp.async.cg.shared.global [%0], [%1], 16;" :: "r"(dst), "l"(src))
#define CPCOMMIT() asm volatile("cp.async.commit_group;")
#define CPWAIT(N)  asm volatile("cp.async.wait_group %0;" :: "n"(N))

#define MBAR_INIT(addr, cnt) \
    asm volatile("mbarrier.init.shared.b64 [%0], %1;" :: "r"(addr), "r"(cnt) : "memory")
#define MBAR_ARRIVE(addr) \
    asm volatile("mbarrier.arrive.shared.b64 _, [%0];" :: "r"(addr) : "memory")
#define CPASYNC_MBAR_ARRIVE(addr) \
    asm volatile("cp.async.mbarrier.arrive.noinc.shared.b64 [%0];" :: "r"(addr) : "memory")

#define MBAR_WAIT(addr, par) do { \
    unsigned _m = (addr), _p = (par), _d; \
    asm volatile("{\n\t.reg .pred p;\n\t" \
        "mbarrier.try_wait.parity.acquire.cta.shared::cta.b64 p, [%1], %2;\n\t" \
        "selp.b32 %0, 1, 0, p;\n\t}" : "=r"(_d) : "r"(_m), "r"(_p) : "memory"); \
    if (!_d) { \
        asm volatile("{\n\t.reg .pred P1;\n\t" \
            "WL%=:\n\t" \
            "mbarrier.try_wait.parity.acquire.cta.shared::cta.b64 P1, [%0], %1, 0x989680;\n\t" \
            "@P1 bra.uni WD%=;\n\t" \
            "bra.uni WL%=;\n\t" \
            "WD%=:\n\t}" :: "r"(_m), "r"(_p) : "memory"); \
    } \
} while (0)

// ---------------------------------------------------------------------------
// tf32-round (weights, natural order)
// ---------------------------------------------------------------------------
__global__ void cvt_tf32(float* __restrict__ dst, const float* __restrict__ src, int n4)
{
    int i = blockIdx.x * blockDim.x + threadIdx.x;
    int stride = gridDim.x * blockDim.x;
    for (; i < n4; i += stride) {
        float4 v = ((const float4*)src)[i];
        ((float4*)dst)[i] = make_float4(f2tff(v.x), f2tff(v.y), f2tff(v.z), f2tff(v.w));
    }
}

// ---------------------------------------------------------------------------
// tf32-round + octet permute [0,4,1,5,2,6,3,7]  (H / activations)
// ---------------------------------------------------------------------------
__global__ void cvt_tf32_perm(float* __restrict__ dst, const float* __restrict__ src, int n8)
{
    int i = blockIdx.x * blockDim.x + threadIdx.x;
    int stride = gridDim.x * blockDim.x;
    for (; i < n8; i += stride) {
        float4 a = ((const float4*)src)[2 * i];
        float4 b = ((const float4*)src)[2 * i + 1];
        ((float4*)dst)[2 * i] =
            make_float4(f2tff(a.x), f2tff(b.x), f2tff(a.y), f2tff(b.y));
        ((float4*)dst)[2 * i + 1] =
            make_float4(f2tff(a.z), f2tff(b.z), f2tff(a.w), f2tff(b.w));
    }
}

// ---------------------------------------------------------------------------
// Transpose V[b][s][gd] -> Vt[b*512+gd][s], s-octets permuted.
// ---------------------------------------------------------------------------
__global__ void transpose_v(float* __restrict__ Vt, const float* __restrict__ V)
{
    __shared__ float t[32][33];
    const int s0 = blockIdx.x * 32, gd0 = blockIdx.y * 32, b = blockIdx.z;
    #pragma unroll
    for (int i = 0; i < 4; i++) {
        int row = threadIdx.y + i * 8;
        t[row][threadIdx.x] =
            V[((size_t)b * SS + s0 + row) * KVD + gd0 + threadIdx.x];
    }
    __syncthreads();
    const int j = threadIdx.x;
    const int ssrc = (j & 24) + ((j & 1) ? 4 + ((j & 7) >> 1) : ((j & 7) >> 1));
    #pragma unroll
    for (int i = 0; i < 4; i++) {
        int gdl = threadIdx.y + i * 8;
        Vt[((size_t)b * KVD + gd0 + gdl) * SS + s0 + j] = t[ssrc][gdl];
    }
}

// ---------------------------------------------------------------------------
// tf32 GEMM + bias, 512 threads / 16 warps (4m x 4n), CTA tile 128x256x32,
// warp tile 32x64 (acc=64 regs -> ~115 regs/thread -> 16 warps/SM).
// z = blockIdx.z + zoff: 0=Q (N=2048, scaled, octet-perm out),
// 1=K (octet-perm out), 2=V (plain out). Exact grids per launch.
// As[m][k] stride 40 (conflict-free LDS.64 a-frags); Bs[k][n] stride 264.
// ---------------------------------------------------------------------------
#define GA 5120
#define GB 8448
#define GBUF (GA + GB)
#define GEMM_SMEM_BYTES (GBUF * 2 * 4)

__device__ __forceinline__ void gemm_stage(
    unsigned sA, unsigned sB, const float* __restrict__ X, const float* __restrict__ W,
    int N, int bm, int bn, int k0, int tid)
{
    #pragma unroll
    for (int it = 0; it < 2; it++) {              // A: 128 x 32 (1024 chunks)
        int f = tid + it * 512;
        int m  = f >> 3;
        int kq = (f & 7) * 4;
        CP16(sA + (m * 40 + kq) * 4, X + (size_t)(bm + m) * DD + k0 + kq);
    }
    #pragma unroll
    for (int it = 0; it < 4; it++) {              // B: 32 x 256 (2048 chunks)
        int f = tid + it * 512;
        int kk = f >> 6;
        int nq = (f & 63) * 4;
        CP16(sB + (kk * 264 + nq) * 4, W + (size_t)(k0 + kk) * N + bn + nq);
    }
}

__global__ __launch_bounds__(512) void gemm_tf32(
    const float* __restrict__ X,
    const float* __restrict__ Wq, const float* __restrict__ bq, float* __restrict__ Yq,
    const float* __restrict__ Wk, const float* __restrict__ bk, float* __restrict__ Yk,
    const float* __restrict__ Wv, const float* __restrict__ bv, float* __restrict__ Yv,
    float qscale, int zoff)
{
    const int z = blockIdx.z + zoff;
    const float* __restrict__ W  = (z == 0) ? Wq : (z == 1) ? Wk : Wv;
    const float* __restrict__ bi = (z == 0) ? bq : (z == 1) ? bk : bv;
    float*       __restrict__ Y  = (z == 0) ? Yq : (z == 1) ? Yk : Yv;
    const int   N      = (z == 0) ? DD : KVD;
    const float oscale = (z == 0) ? qscale : 1.0f;
    const int   permv  = (z == 2) ? 0 : 1;

    extern __shared__ unsigned smg[];
    const int tid  = threadIdx.x;
    const int lane = tid & 31;
    const int wid  = tid >> 5;     // 0..15
    const int wm   = wid >> 2;     // 0..3
    const int wn   = wid & 3;      // 0..3
    const int lr   = lane >> 2;
    const int lc   = lane & 3;
    const int bm = blockIdx.y * 128;
    const int bn = blockIdx.x * 256;

    unsigned sbase = (unsigned)__cvta_generic_to_shared(smg);

    float acc[2][8][4];
    #pragma unroll
    for (int i = 0; i < 2; i++)
        #pragma unroll
        for (int j = 0; j < 8; j++)
            #pragma unroll
            for (int k = 0; k < 4; k++) acc[i][j][k] = 0.f;

    const int nK = DD / 32;
    gemm_stage(sbase, sbase + GA * 4, X, W, N, bm, bn, 0, tid);
    CPCOMMIT();

    for (int i = 0; i < nK; i++) {
        CPWAIT(0);
        __syncthreads();
        if (i + 1 < nK) {
            unsigned boff = ((i + 1) & 1) * GBUF * 4;
            gemm_stage(sbase + boff, sbase + boff + GA * 4,
                       X, W, N, bm, bn, (i + 1) * 32, tid);
            CPCOMMIT();
        }
        const unsigned* As = smg + (i & 1) * GBUF;
        const unsigned* Bs = As + GA;

        #pragma unroll
        for (int s = 0; s < 4; s++) {
            const int c = s * 8 + lc;
            unsigned af[2][4], bf[8][2];
            #pragma unroll
            for (int mt = 0; mt < 2; mt++) {
                int r = wm * 32 + mt * 16 + lr;
                uint2 u1 = *(const uint2*)&As[r * 40 + s * 8 + 2 * lc];
                uint2 u2 = *(const uint2*)&As[(r + 8) * 40 + s * 8 + 2 * lc];
                af[mt][0] = u1.x; af[mt][1] = u2.x;
                af[mt][2] = u1.y; af[mt][3] = u2.y;
            }
            #pragma unroll
            for (int nt = 0; nt < 8; nt++) {
                int n = wn * 64 + nt * 8 + lr;
                bf[nt][0] = Bs[c * 264 + n];
                bf[nt][1] = Bs[(c + 4) * 264 + n];
            }
            #pragma unroll
            for (int mt = 0; mt < 2; mt++)
                #pragma unroll
                for (int nt = 0; nt < 8; nt++)
                    mma_tf32(acc[mt][nt], af[mt], bf[nt]);
        }
        __syncthreads();
    }

    const int p0 = (lc < 2) ? 4 * lc : 4 * lc - 7;       // perm pos of col 2lc
    const int p1 = (lc < 2) ? 4 * lc + 2 : 4 * lc - 5;   // perm pos of col 2lc+1
    #pragma unroll
    for (int mt = 0; mt < 2; mt++) {
        int r = bm + wm * 32 + mt * 16 + lr;
        #pragma unroll
        for (int nt = 0; nt < 8; nt++) {
            int base = bn + wn * 64 + nt * 8;
            float bv0 = bi[base + 2 * lc], bv1 = bi[base + 2 * lc + 1];
            float v00 = f2tff((acc[mt][nt][0] + bv0) * oscale);
            float v01 = f2tff((acc[mt][nt][1] + bv1) * oscale);
            float v10 = f2tff((acc[mt][nt][2] + bv0) * oscale);
            float v11 = f2tff((acc[mt][nt][3] + bv1) * oscale);
            if (permv) {
                Y[(size_t)r * N + base + p0] = v00;
                Y[(size_t)r * N + base + p1] = v01;
                Y[(size_t)(r + 8) * N + base + p0] = v10;
                Y[(size_t)(r + 8) * N + base + p1] = v11;
            } else {
                *(float2*)(Y + (size_t)r * N + base + 2 * lc) = make_float2(v00, v01);
                *(float2*)(Y + (size_t)(r + 8) * N + base + 2 * lc) = make_float2(v10, v11);
            }
        }
    }
}

// ---------------------------------------------------------------------------
// tf32 flash attention — byte-identical to the round-6/round-9 kernel
// (best passing: 803us total). Q register-resident, K/Vt triple-buffered,
// no __syncthreads in main loop, octet-perm LDS.64 fragment loads.
// ---------------------------------------------------------------------------
#define KSLOT 8704
#define VSLOT 9216
#define VBASE 26112
#define BARW  53760
#define ATTN_SMEM_BYTES (53776 * 4)

__global__ __launch_bounds__(256) void attn_tf32(
    const float* __restrict__ Q, const float* __restrict__ K,
    const float* __restrict__ Vt, float* __restrict__ O)
{
    extern __shared__ float sm[];

    const int tid  = threadIdx.x;
    const int lane = tid & 31;
    const int wid  = tid >> 5;
    const int lr = lane >> 2;
    const int lc = lane & 3;
    const int r0 = 16 * wid + lr;
    const int q0 = blockIdx.x * 128;
    const int h  = blockIdx.y;
    const int b  = blockIdx.z;
    const int g  = h & (HKV - 1);

    const float* Qb = Q  + (size_t)b * SS * DD  + (size_t)h * HD;
    const float* Kb = K  + (size_t)b * SS * KVD + (size_t)g * HD;
    const float* Vb = Vt + ((size_t)b * KVD + (size_t)g * HD) * SS;

    unsigned sbase = (unsigned)__cvta_generic_to_shared(sm);

    if (tid == 0) {
        #pragma unroll
        for (int s = 0; s < 3; s++) {
            MBAR_INIT(sbase + (BARW + 2 * s) * 4, 256);      // full[s]
            MBAR_INIT(sbase + (BARW + 6 + 2 * s) * 4, 256);  // empty[s]
        }
    }

    // --- Prologue: stage Q through K region, move to registers ---
    #pragma unroll
    for (int it = 0; it < 16; it++) {
        int f = tid + it * 256;
        int q  = f >> 5;
        int dq = (f & 31) * 4;
        CP16(sbase + (q * 136 + dq) * 4, Qb + (size_t)(q0 + q) * DD + dq);
    }
    CPCOMMIT();
    CPWAIT(0);
    __syncthreads();            // Q staged + barriers initialized

    unsigned qa[16][4];
    {
        const unsigned* Qs = (const unsigned*)sm;
        #pragma unroll
        for (int st = 0; st < 16; st++) {
            uint2 u1 = *(const uint2*)&Qs[r0 * 136 + st * 8 + 2 * lc];
            uint2 u2 = *(const uint2*)&Qs[(r0 + 8) * 136 + st * 8 + 2 * lc];
            qa[st][0] = u1.x; qa[st][1] = u2.x;
            qa[st][2] = u1.y; qa[st][3] = u2.y;
        }
    }
    __syncthreads();            // all Q reads done before K slot 0/1 fills

    // --- Fill slots 0 and 1 ---
    #pragma unroll
    for (int s = 0; s < 2; s++) {
        unsigned sKs = sbase + s * KSLOT * 4;
        unsigned sVs = sbase + (VBASE + s * VSLOT) * 4;
        #pragma unroll
        for (int it = 0; it < 8; it++) {
            int f = tid + it * 256;
            int key = f >> 5;
            int dq  = (f & 31) * 4;
            CP16(sKs + (key * 136 + dq) * 4,
                 Kb + (size_t)(s * 64 + key) * KVD + dq);
        }
        #pragma unroll
        for (int it = 0; it < 8; it++) {
            int f = tid + it * 256;
            int d  = f >> 4;
            int sq = (f & 15) * 4;
            CP16(sVs + (d * 72 + sq) * 4, Vb + (size_t)d * SS + s * 64 + sq);
        }
        CPASYNC_MBAR_ARRIVE(sbase + (BARW + 2 * s) * 4);
    }

    float o[16][4];
    #pragma unroll
    for (int dt = 0; dt < 16; dt++)
        #pragma unroll
        for (int k = 0; k < 4; k++) o[dt][k] = 0.f;
    float rm0 = -INFINITY, rm1 = -INFINITY, rl0 = 0.f, rl1 = 0.f;

    const int sAsrc = lr * 4 + (lc >> 1);
    const int sBsrc = sAsrc + 2;
    const bool oddc = (lc & 1);

    #pragma unroll 1
    for (int kt = 0; kt < NT; kt++) {
        // --- producer: fill slot (kt+2)%3 for tile kt+2 ---
        const int fs = kt + 2;
        if (fs < NT) {
            const int slot = fs % 3;
            if (fs >= 3) MBAR_WAIT(sbase + (BARW + 6 + 2 * slot) * 4,
                                   (unsigned)(((fs / 3) - 1) & 1));
            unsigned sKs = sbase + slot * KSLOT * 4;
            unsigned sVs = sbase + (VBASE + slot * VSLOT) * 4;
            #pragma unroll
            for (int it = 0; it < 8; it++) {
                int f = tid + it * 256;
                int key = f >> 5;
                int dq  = (f & 31) * 4;
                CP16(sKs + (key * 136 + dq) * 4,
                     Kb + (size_t)(fs * 64 + key) * KVD + dq);
            }
            #pragma unroll
            for (int it = 0; it < 8; it++) {
                int f = tid + it * 256;
                int d  = f >> 4;
                int sq = (f & 15) * 4;
                CP16(sVs + (d * 72 + sq) * 4, Vb + (size_t)d * SS + fs * 64 + sq);
            }
            CPASYNC_MBAR_ARRIVE(sbase + (BARW + 2 * slot) * 4);
        }

        // --- consumer: wait slot kt%3 full ---
        const int slot = kt % 3;
        MBAR_WAIT(sbase + (BARW + 2 * slot) * 4, (unsigned)((kt / 3) & 1));
        const unsigned* Kst = (const unsigned*)(sm + slot * KSLOT);
        const unsigned* Vts = (const unsigned*)(sm + VBASE + slot * VSLOT);

        // ---- S = Q K^T ----
        float sacc[8][4];
        #pragma unroll
        for (int nt = 0; nt < 8; nt++)
            #pragma unroll
            for (int k = 0; k < 4; k++) sacc[nt][k] = 0.f;

        #pragma unroll
        for (int st = 0; st < 16; st++) {
            #pragma unroll
            for (int nt = 0; nt < 8; nt++) {
                uint2 bu = *(const uint2*)&Kst[(8 * nt + lr) * 136 + st * 8 + 2 * lc];
                unsigned bf[2] = { bu.x, bu.y };
                mma_tf32(sacc[nt], qa[st], bf);
            }
        }

        // ---- warp-private online softmax; P -> a-frags via shuffles ----
        float m0 = sacc[0][0], m1 = sacc[0][2];
        #pragma unroll
        for (int nt = 0; nt < 8; nt++) {
            m0 = fmaxf(m0, fmaxf(sacc[nt][0], sacc[nt][1]));
            m1 = fmaxf(m1, fmaxf(sacc[nt][2], sacc[nt][3]));
        }
        m0 = fmaxf(m0, __shfl_xor_sync(0xffffffffu, m0, 1));
        m0 = fmaxf(m0, __shfl_xor_sync(0xffffffffu, m0, 2));
        m1 = fmaxf(m1, __shfl_xor_sync(0xffffffffu, m1, 1));
        m1 = fmaxf(m1, __shfl_xor_sync(0xffffffffu, m1, 2));
        float mn0 = fmaxf(rm0, m0), mn1 = fmaxf(rm1, m1);
        float al0 = __expf(rm0 - mn0), al1 = __expf(rm1 - mn1);
        float sum0 = 0.f, sum1 = 0.f;
        unsigned pa[8][4];
        #pragma unroll
        for (int nt = 0; nt < 8; nt++) {
            float f0 = __expf(sacc[nt][0] - mn0);
            float f1 = __expf(sacc[nt][1] - mn0);
            float f2 = __expf(sacc[nt][2] - mn1);
            float f3 = __expf(sacc[nt][3] - mn1);
            sum0 += f0 + f1;
            sum1 += f2 + f3;
            unsigned t0 = f2tf(f0), t1 = f2tf(f1), t2 = f2tf(f2), t3 = f2tf(f3);
            unsigned e0 = __shfl_sync(0xffffffffu, t0, sAsrc);
            unsigned o0 = __shfl_sync(0xffffffffu, t1, sAsrc);
            unsigned e1 = __shfl_sync(0xffffffffu, t2, sAsrc);
            unsigned o1 = __shfl_sync(0xffffffffu, t3, sAsrc);
            unsigned e2 = __shfl_sync(0xffffffffu, t0, sBsrc);
            unsigned o2 = __shfl_sync(0xffffffffu, t1, sBsrc);
            unsigned e3 = __shfl_sync(0xffffffffu, t2, sBsrc);
            unsigned o3 = __shfl_sync(0xffffffffu, t3, sBsrc);
            pa[nt][0] = oddc ? o0 : e0;
            pa[nt][1] = oddc ? o1 : e1;
            pa[nt][2] = oddc ? o2 : e2;
            pa[nt][3] = oddc ? o3 : e3;
        }
        sum0 += __shfl_xor_sync(0xffffffffu, sum0, 1);
        sum0 += __shfl_xor_sync(0xffffffffu, sum0, 2);
        sum1 += __shfl_xor_sync(0xffffffffu, sum1, 1);
        sum1 += __shfl_xor_sync(0xffffffffu, sum1, 2);
        rl0 = rl0 * al0 + sum0;  rm0 = mn0;
        rl1 = rl1 * al1 + sum1;  rm1 = mn1;
        #pragma unroll
        for (int dt = 0; dt < 16; dt++) {
            o[dt][0] *= al0;  o[dt][1] *= al0;
            o[dt][2] *= al1;  o[dt][3] *= al1;
        }

        // ---- O += P V ----
        #pragma unroll
        for (int nt = 0; nt < 8; nt++) {
            #pragma unroll
            for (int dt = 0; dt < 16; dt++) {
                uint2 vu = *(const uint2*)&Vts[(8 * dt + lr) * 72 + nt * 8 + 2 * lc];
                unsigned bf[2] = { vu.x, vu.y };
                mma_tf32(o[dt], pa[nt], bf);
            }
        }

        // release slot
        MBAR_ARRIVE(sbase + (BARW + 6 + 2 * slot) * 4);
    }

    // Epilogue
    float* Ob = O + (size_t)b * SS * DD + (size_t)h * HD;
    float inv0 = 1.f / rl0, inv1 = 1.f / rl1;
    #pragma unroll
    for (int dt = 0; dt < 16; dt++) {
        int cc = 8 * dt + 2 * lc;
        *(float2*)(Ob + (size_t)(q0 + r0) * DD + cc) =
            make_float2(o[dt][0] * inv0, o[dt][1] * inv0);
        *(float2*)(Ob + (size_t)(q0 + r0 + 8) * DD + cc) =
            make_float2(o[dt][2] * inv1, o[dt][3] * inv1);
    }
}

// ---------------------------------------------------------------------------
// Launch: two-stream fork/join (round-9 schedule).
// ---------------------------------------------------------------------------
extern "C" void kernel_launch(void* const* d_in, const int* in_sizes, int n_in,
                              void* d_out, int out_size)
{
    (void)in_sizes; (void)n_in; (void)out_size;
    const float* H  = (const float*)d_in[0];
    const float* Wq = (const float*)d_in[1];
    const float* bq = (const float*)d_in[2];
    const float* Wk = (const float*)d_in[3];
    const float* bk = (const float*)d_in[4];
    const float* Wv = (const float*)d_in[5];
    const float* bv = (const float*)d_in[6];
    float* out = (float*)d_out;

    static cudaStream_t s2 = 0;
    static cudaEvent_t eFork = 0, eH = 0, eKV = 0;
    if (s2 == 0) {
        cudaStreamCreateWithFlags(&s2, cudaStreamNonBlocking);
        cudaEventCreateWithFlags(&eFork, cudaEventDisableTiming);
        cudaEventCreateWithFlags(&eH,    cudaEventDisableTiming);
        cudaEventCreateWithFlags(&eKV,   cudaEventDisableTiming);
    }

    float *Qp, *Kp, *Vp, *Vtp, *Hp, *Wqp, *Wkp, *Wvp;
    cudaGetSymbolAddress((void**)&Qp,  g_Q);
    cudaGetSymbolAddress((void**)&Kp,  g_K);
    cudaGetSymbolAddress((void**)&Vp,  g_V);
    cudaGetSymbolAddress((void**)&Vtp, g_Vt);
    cudaGetSymbolAddress((void**)&Hp,  g_H);
    cudaGetSymbolAddress((void**)&Wqp, g_Wq);
    cudaGetSymbolAddress((void**)&Wkp, g_Wk);
    cudaGetSymbolAddress((void**)&Wvp, g_Wv);

    cudaFuncSetAttribute(gemm_tf32,
                         cudaFuncAttributeMaxDynamicSharedMemorySize, GEMM_SMEM_BYTES);
    cudaFuncSetAttribute(attn_tf32,
                         cudaFuncAttributeMaxDynamicSharedMemorySize, ATTN_SMEM_BYTES);

    const float scale = 0.08838834764831845f;  // 1/sqrt(128)
    const int nb = 148 * 8;

    // Fork s2 off the capture/main stream.
    cudaEventRecord(eFork, 0);
    cudaStreamWaitEvent(s2, eFork, 0);

    // Stream 0: H (octet-perm) + Wq cvt.
    cvt_tf32_perm<<<nb, 256>>>(Hp, H, (int)((size_t)MM * DD / 8));
    cvt_tf32<<<nb, 256>>>(Wqp, Wq, (int)((size_t)DD * DD / 4));
    cudaEventRecord(eH, 0);

    // Stream s2: Wk/Wv cvt (independent of H), then wait for H.
    cvt_tf32<<<nb, 256, 0, s2>>>(Wkp, Wk, (int)((size_t)DD * KVD / 4));
    cvt_tf32<<<nb, 256, 0, s2>>>(Wvp, Wv, (int)((size_t)DD * KVD / 4));
    cudaStreamWaitEvent(s2, eH, 0);

    // Stream 0: Q projection (z=0 only, exact grid, 512 threads).
    gemm_tf32<<<dim3(DD / 256, MM / 128, 1), 512, GEMM_SMEM_BYTES>>>(
        Hp, Wqp, bq, Qp, Wkp, bk, Kp, Wvp, bv, Vp, scale, 0);

    // Stream s2: K + V projections (z=1,2, exact grid), then V transpose.
    gemm_tf32<<<dim3(KVD / 256, MM / 128, 2), 512, GEMM_SMEM_BYTES, s2>>>(
        Hp, Wqp, bq, Qp, Wkp, bk, Kp, Wvp, bv, Vp, scale, 1);
    transpose_v<<<dim3(SS / 32, KVD / 32, BB), dim3(32, 8), 0, s2>>>(Vtp, Vp);
    cudaEventRecord(eKV, s2);

    // Join: attention needs Q (stream 0) and K/Vt (s2).
    cudaStreamWaitEvent(0, eKV, 0);
    attn_tf32<<<dim3(SS / 128, HQ, BB), 256, ATTN_SMEM_BYTES>>>(Qp, Kp, Vtp, out);
}

// round 13
// speedup vs baseline: 2.0584x; 1.8466x over previous
#include <cuda_runtime.h>
#include <cuda_fp16.h>
#include <math.h>

#define BB   2
#define SS   2048
#define DD   2048
#define HQ   16
#define HKV  4
#define HD   128
#define KVD  512
#define MM   (BB*SS)
#define NT   (SS/64)

// Scratch (device globals) — fp16 operands, fp32 I/O
__device__ __half g_Q[(size_t)MM * DD];    // [token][d]  d pair-permuted, scaled
__device__ __half g_K[(size_t)MM * KVD];   // [token][gd] d pair-permuted
__device__ __half g_V[(size_t)MM * KVD];   // [token][gd] plain
__device__ __half g_Vt[(size_t)BB * KVD * SS]; // h2[b*512+gd][s/2], s pair-permuted
__device__ __half g_H[(size_t)MM * DD];    // fp16, k pair-permuted
__device__ __half g_Wq[(size_t)DD * DD];   // h2[k/2][n] (k-pair interleaved)
__device__ __half g_Wk[(size_t)DD * KVD];
__device__ __half g_Wv[(size_t)DD * KVD];

__device__ __forceinline__ unsigned h2pack(float lo, float hi) {
    __half2 h = __floats2half2_rn(lo, hi);
    return *reinterpret_cast<unsigned*>(&h);
}

__device__ __forceinline__ void mma_f16(float c[4], const unsigned a[4], const unsigned b[2]) {
    asm volatile(
        "mma.sync.aligned.m16n8k16.row.col.f32.f16.f16.f32 "
        "{%0,%1,%2,%3},{%4,%5,%6,%7},{%8,%9},{%0,%1,%2,%3};"
        : "+f"(c[0]), "+f"(c[1]), "+f"(c[2]), "+f"(c[3])
        : "r"(a[0]), "r"(a[1]), "r"(a[2]), "r"(a[3]), "r"(b[0]), "r"(b[1]));
}

#define CP16(dst, src) \
    asm volatile("cp.async.cg.shared.global [%0], [%1], 16;" :: "r"(dst), "l"(src))
#define CPCOMMIT() asm volatile("cp.async.commit_group;")
#define CPWAIT(N)  asm volatile("cp.async.wait_group %0;" :: "n"(N))

#define MBAR_INIT(addr, cnt) \
    asm volatile("mbarrier.init.shared.b64 [%0], %1;" :: "r"(addr), "r"(cnt) : "memory")
#define MBAR_ARRIVE(addr) \
    asm volatile("mbarrier.arrive.shared.b64 _, [%0];" :: "r"(addr) : "memory")
#define CPASYNC_MBAR_ARRIVE(addr) \
    asm volatile("cp.async.mbarrier.arrive.noinc.shared.b64 [%0];" :: "r"(addr) : "memory")

#define MBAR_WAIT(addr, par) do { \
    unsigned _m = (addr), _p = (par), _d; \
    asm volatile("{\n\t.reg .pred p;\n\t" \
        "mbarrier.try_wait.parity.acquire.cta.shared::cta.b64 p, [%1], %2;\n\t" \
        "selp.b32 %0, 1, 0, p;\n\t}" : "=r"(_d) : "r"(_m), "r"(_p) : "memory"); \
    if (!_d) { \
        asm volatile("{\n\t.reg .pred P1;\n\t" \
            "WL%=:\n\t" \
            "mbarrier.try_wait.parity.acquire.cta.shared::cta.b64 P1, [%0], %1, 0x989680;\n\t" \
            "@P1 bra.uni WD%=;\n\t" \
            "bra.uni WL%=;\n\t" \
            "WD%=:\n\t}" :: "r"(_m), "r"(_p) : "memory"); \
    } \
} while (0)

// ---------------------------------------------------------------------------
// H: fp32 -> fp16, pairs permuted [P0,P4,P1,P5,P2,P6,P3,P7] per 16-value group.
// ---------------------------------------------------------------------------
__global__ void cvt_h(__half* __restrict__ dst, const float* __restrict__ src, int n16)
{
    int i = blockIdx.x * blockDim.x + threadIdx.x;
    const int stride = gridDim.x * blockDim.x;
    for (; i < n16; i += stride) {
        const float4* s = (const float4*)src + 4 * (size_t)i;
        float4 s0 = s[0], s1 = s[1], s2 = s[2], s3 = s[3];
        uint4 o0, o1;
        o0.x = h2pack(s0.x, s0.y);  // P0
        o0.y = h2pack(s2.x, s2.y);  // P4
        o0.z = h2pack(s0.z, s0.w);  // P1
        o0.w = h2pack(s2.z, s2.w);  // P5
        o1.x = h2pack(s1.x, s1.y);  // P2
        o1.y = h2pack(s3.x, s3.y);  // P6
        o1.z = h2pack(s1.z, s1.w);  // P3
        o1.w = h2pack(s3.z, s3.w);  // P7
        uint4* o = (uint4*)dst + 2 * (size_t)i;
        o[0] = o0;
        o[1] = o1;
    }
}

// ---------------------------------------------------------------------------
// W: fp32 [k][n] -> h2 [k/2][n], element (i,n) = half2(W[2i][n], W[2i+1][n]).
// ---------------------------------------------------------------------------
__global__ void cvt_w(__half* __restrict__ dst, const float* __restrict__ src,
                      int K2, int N)
{
    int j = blockIdx.x * blockDim.x + threadIdx.x;
    const int stride = gridDim.x * blockDim.x;
    const int nq = N / 4;
    const int total = K2 * nq;
    for (; j < total; j += stride) {
        int i  = j / nq;
        int n4 = (j % nq) * 4;
        float4 a = *(const float4*)(src + (size_t)(2 * i) * N + n4);
        float4 b = *(const float4*)(src + (size_t)(2 * i + 1) * N + n4);
        uint4 o;
        o.x = h2pack(a.x, b.x);
        o.y = h2pack(a.y, b.y);
        o.z = h2pack(a.z, b.z);
        o.w = h2pack(a.w, b.w);
        *((uint4*)dst + (size_t)i * nq + (n4 >> 2)) = o;
    }
}

// ---------------------------------------------------------------------------
// V half [b][s][gd] -> Vt h2 [b*512+gd][s/2], s pairs permuted per 16-s group.
// Tile: 64 s x 32 gd per block; block (32, 8).
// ---------------------------------------------------------------------------
__global__ void transpose_v(__half* __restrict__ Vt, const __half* __restrict__ V)
{
    __shared__ __half t[64][36];
    const int s0 = blockIdx.x * 64, gd0 = blockIdx.y * 32, b = blockIdx.z;
    #pragma unroll
    for (int i = 0; i < 8; i++) {
        int e = (threadIdx.y + i * 8) * 32 + threadIdx.x;  // 0..2047
        int srow = e >> 5, gcol = e & 31;
        t[srow][gcol] = V[((size_t)b * SS + s0 + srow) * KVD + gd0 + gcol];
    }
    __syncthreads();
    const int x = threadIdx.x;                 // s2 slot 0..31
    const int grp = x >> 3, qq = x & 7;
    const int lp = (qq & 1) ? (qq >> 1) + 4 : (qq >> 1);
    const int sl = grp * 16 + 2 * lp;
    unsigned* Vt2 = (unsigned*)Vt;
    #pragma unroll
    for (int i = 0; i < 4; i++) {
        int gd = threadIdx.y + i * 8;          // 0..31
        float lo = __half2float(t[sl][gd]);    // cheap; or pack halves directly
        float hi = __half2float(t[sl + 1][gd]);
        Vt2[((size_t)b * KVD + gd0 + gd) * (SS / 2) + (s0 >> 1) + x] = h2pack(lo, hi);
    }
}

// ---------------------------------------------------------------------------
// fp16 GEMM + bias: 8 warps (2m x 4n), CTA 128x256x32, warp tile 64x64.
// A: h2 SMEM stride 24 words; B: h2 SMEM [k2][n] stride 264 words.
// z = blockIdx.z + zoff: 0=Q (N=2048, scaled, pair-perm out),
// 1=K (pair-perm out), 2=V (plain out).
// ---------------------------------------------------------------------------
#define GA 3072
#define GB 4224
#define GBUF (GA + GB)
#define GEMM_SMEM_BYTES (GBUF * 2 * 4)

__device__ __forceinline__ void gemm_stage(
    unsigned sA, unsigned sB, const __half* __restrict__ X, const unsigned* __restrict__ W2,
    int N, int bm, int bn, int k0, int tid)
{
    #pragma unroll
    for (int it = 0; it < 2; it++) {              // A: 128 rows x 4 chunks
        int f = tid + it * 256;
        int m  = f >> 2;
        int ch = f & 3;
        CP16(sA + (m * 24 + 4 * ch) * 4, X + (size_t)(bm + m) * DD + k0 + ch * 8);
    }
    const int k02 = k0 >> 1;
    #pragma unroll
    for (int it = 0; it < 4; it++) {              // B: 16 k2-rows x 64 chunks
        int f = tid + it * 256;
        int kk2 = f >> 6;
        int nq  = (f & 63) * 4;
        CP16(sB + (kk2 * 264 + nq) * 4, W2 + (size_t)(k02 + kk2) * N + bn + nq);
    }
}

__global__ __launch_bounds__(256) void gemm_f16(
    const __half* __restrict__ X,
    const __half* __restrict__ Wq, const float* __restrict__ bq, __half* __restrict__ Yq,
    const __half* __restrict__ Wk, const float* __restrict__ bk, __half* __restrict__ Yk,
    const __half* __restrict__ Wv, const float* __restrict__ bv, __half* __restrict__ Yv,
    float qscale, int zoff)
{
    const int z = blockIdx.z + zoff;
    const __half* __restrict__ W  = (z == 0) ? Wq : (z == 1) ? Wk : Wv;
    const float*  __restrict__ bi = (z == 0) ? bq : (z == 1) ? bk : bv;
    __half*       __restrict__ Y  = (z == 0) ? Yq : (z == 1) ? Yk : Yv;
    const int   N      = (z == 0) ? DD : KVD;
    const float oscale = (z == 0) ? qscale : 1.0f;
    const int   permv  = (z == 2) ? 0 : 1;

    extern __shared__ unsigned smg[];
    const int tid  = threadIdx.x;
    const int lane = tid & 31;
    const int wid  = tid >> 5;
    const int wm   = wid >> 2;     // 0..1
    const int wn   = wid & 3;      // 0..3
    const int lr   = lane >> 2;
    const int lc   = lane & 3;
    const int bm = blockIdx.y * 128;
    const int bn = blockIdx.x * 256;

    unsigned sbase = (unsigned)__cvta_generic_to_shared(smg);

    float acc[4][8][4];
    #pragma unroll
    for (int i = 0; i < 4; i++)
        #pragma unroll
        for (int j = 0; j < 8; j++)
            #pragma unroll
            for (int k = 0; k < 4; k++) acc[i][j][k] = 0.f;

    const int nK = DD / 32;
    gemm_stage(sbase, sbase + GA * 4, X, (const unsigned*)W, N, bm, bn, 0, tid);
    CPCOMMIT();

    for (int i = 0; i < nK; i++) {
        CPWAIT(0);
        __syncthreads();
        if (i + 1 < nK) {
            unsigned boff = ((i + 1) & 1) * GBUF * 4;
            gemm_stage(sbase + boff, sbase + boff + GA * 4,
                       X, (const unsigned*)W, N, bm, bn, (i + 1) * 32, tid);
            CPCOMMIT();
        }
        const unsigned* As = smg + (i & 1) * GBUF;
        const unsigned* Bs = As + GA;

        #pragma unroll
        for (int g = 0; g < 2; g++) {             // two k16 chunks per iter
            unsigned af[4][4], bf[8][2];
            #pragma unroll
            for (int mt = 0; mt < 4; mt++) {
                int r = wm * 64 + mt * 16 + lr;
                uint2 u1 = *(const uint2*)&As[r * 24 + 8 * g + 2 * lc];
                uint2 u2 = *(const uint2*)&As[(r + 8) * 24 + 8 * g + 2 * lc];
                af[mt][0] = u1.x; af[mt][1] = u2.x;
                af[mt][2] = u1.y; af[mt][3] = u2.y;
            }
            #pragma unroll
            for (int nt = 0; nt < 8; nt++) {
                int n = wn * 64 + nt * 8 + lr;
                bf[nt][0] = Bs[(8 * g + lc) * 264 + n];
                bf[nt][1] = Bs[(8 * g + lc + 4) * 264 + n];
            }
            #pragma unroll
            for (int mt = 0; mt < 4; mt++)
                #pragma unroll
                for (int nt = 0; nt < 8; nt++)
                    mma_f16(acc[mt][nt], af[mt], bf[nt]);
        }
        __syncthreads();
    }

    #pragma unroll
    for (int mt = 0; mt < 4; mt++) {
        int r = bm + wm * 64 + mt * 16 + lr;
        #pragma unroll
        for (int nt = 0; nt < 8; nt++) {
            int base = bn + wn * 64 + nt * 8;
            int c0 = base + 2 * lc;
            float bv0 = bi[c0], bv1 = bi[c0 + 1];
            unsigned v0 = h2pack((acc[mt][nt][0] + bv0) * oscale,
                                 (acc[mt][nt][1] + bv1) * oscale);
            unsigned v1 = h2pack((acc[mt][nt][2] + bv0) * oscale,
                                 (acc[mt][nt][3] + bv1) * oscale);
            int idx;
            if (permv) {
                int L = (c0 & 15) >> 1;
                int phys = (L < 4) ? 2 * L : 2 * L - 7;
                idx = (c0 & ~15) + 2 * phys;
            } else {
                idx = c0;
            }
            *(unsigned*)(Y + (size_t)r * N + idx) = v0;
            *(unsigned*)(Y + (size_t)(r + 8) * N + idx) = v1;
        }
    }
}

// ---------------------------------------------------------------------------
// fp16 flash attention. 128 q-rows/CTA, 8 warps x 16 rows; 64-key tiles;
// K/Vt triple-buffered (combined slots), no __syncthreads in main loop.
// Q register-resident (32 regs). P->a-frag needs NO shuffles with k16 frags.
// SMEM words: K 3x(64x72)=13824 | Vt 3x(128x40)=15360 | bars.
// ---------------------------------------------------------------------------
#define KSLOT 4608
#define VSLOT 5120
#define VBASE 13824
#define BARW  29184
#define ATTN_SMEM_BYTES (29200 * 4)

__global__ __launch_bounds__(256) void attn_f16(
    const __half* __restrict__ Q, const __half* __restrict__ K,
    const __half* __restrict__ Vt, float* __restrict__ O)
{
    extern __shared__ unsigned sm[];

    const int tid  = threadIdx.x;
    const int lane = tid & 31;
    const int wid  = tid >> 5;
    const int lr = lane >> 2;
    const int lc = lane & 3;
    const int r0 = 16 * wid + lr;
    const int q0 = blockIdx.x * 128;
    const int h  = blockIdx.y;
    const int b  = blockIdx.z;
    const int g  = h & (HKV - 1);

    const __half* Qb = Q + (size_t)b * SS * DD  + (size_t)h * HD;
    const __half* Kb = K + (size_t)b * SS * KVD + (size_t)g * HD;
    const unsigned* Vb2 = (const unsigned*)Vt + ((size_t)b * KVD + (size_t)g * HD) * (SS / 2);

    unsigned sbase = (unsigned)__cvta_generic_to_shared(sm);

    if (tid == 0) {
        #pragma unroll
        for (int s = 0; s < 3; s++) {
            MBAR_INIT(sbase + (BARW + 2 * s) * 4, 256);      // full[s]
            MBAR_INIT(sbase + (BARW + 6 + 2 * s) * 4, 256);  // empty[s]
        }
    }

    // --- Prologue: stage Q through K region (stride 72 words), to registers ---
    #pragma unroll
    for (int it = 0; it < 8; it++) {
        int f = tid + it * 256;          // 0..2047 (128 rows x 16 chunks)
        int q  = f >> 4;
        int ch = f & 15;
        CP16(sbase + (q * 72 + 4 * ch) * 4, Qb + (size_t)(q0 + q) * DD + ch * 8);
    }
    CPCOMMIT();
    CPWAIT(0);
    __syncthreads();

    unsigned qa[8][4];
    #pragma unroll
    for (int gch = 0; gch < 8; gch++) {
        uint2 u1 = *(const uint2*)&sm[r0 * 72 + 8 * gch + 2 * lc];
        uint2 u2 = *(const uint2*)&sm[(r0 + 8) * 72 + 8 * gch + 2 * lc];
        qa[gch][0] = u1.x; qa[gch][1] = u2.x;
        qa[gch][2] = u1.y; qa[gch][3] = u2.y;
    }
    __syncthreads();            // all Q reads done before K slot fills

    // --- Fill slots 0 and 1 (K + Vt per slot) ---
    #pragma unroll
    for (int s = 0; s < 2; s++) {
        unsigned sKs = sbase + s * KSLOT * 4;
        unsigned sVs = sbase + (VBASE + s * VSLOT) * 4;
        #pragma unroll
        for (int it = 0; it < 4; it++) {
            int f = tid + it * 256;      // 0..1023 (64 rows x 16 chunks)
            int key = f >> 4;
            int ch  = f & 15;
            CP16(sKs + (key * 72 + 4 * ch) * 4,
                 Kb + (size_t)(s * 64 + key) * KVD + ch * 8);
        }
        #pragma unroll
        for (int it = 0; it < 4; it++) {
            int f = tid + it * 256;      // 0..1023 (128 rows x 8 chunks)
            int d  = f >> 3;
            int ch = f & 7;
            CP16(sVs + (d * 40 + 4 * ch) * 4,
                 Vb2 + (size_t)d * (SS / 2) + s * 32 + ch * 4);
        }
        CPASYNC_MBAR_ARRIVE(sbase + (BARW + 2 * s) * 4);
    }

    float o[16][4];
    #pragma unroll
    for (int dt = 0; dt < 16; dt++)
        #pragma unroll
        for (int k = 0; k < 4; k++) o[dt][k] = 0.f;
    float rm0 = -INFINITY, rm1 = -INFINITY, rl0 = 0.f, rl1 = 0.f;

    #pragma unroll 1
    for (int kt = 0; kt < NT; kt++) {
        // --- producer: fill slot (kt+2)%3 ---
        const int fs = kt + 2;
        if (fs < NT) {
            const int slot = fs % 3;
            if (fs >= 3) MBAR_WAIT(sbase + (BARW + 6 + 2 * slot) * 4,
                                   (unsigned)(((fs / 3) - 1) & 1));
            unsigned sKs = sbase + slot * KSLOT * 4;
            unsigned sVs = sbase + (VBASE + slot * VSLOT) * 4;
            #pragma unroll
            for (int it = 0; it < 4; it++) {
                int f = tid + it * 256;
                int key = f >> 4;
                int ch  = f & 15;
                CP16(sKs + (key * 72 + 4 * ch) * 4,
                     Kb + (size_t)(fs * 64 + key) * KVD + ch * 8);
            }
            #pragma unroll
            for (int it = 0; it < 4; it++) {
                int f = tid + it * 256;
                int d  = f >> 3;
                int ch = f & 7;
                CP16(sVs + (d * 40 + 4 * ch) * 4,
                     Vb2 + (size_t)d * (SS / 2) + fs * 32 + ch * 4);
            }
            CPASYNC_MBAR_ARRIVE(sbase + (BARW + 2 * slot) * 4);
        }

        // --- consumer: wait slot kt%3 full ---
        const int slot = kt % 3;
        MBAR_WAIT(sbase + (BARW + 2 * slot) * 4, (unsigned)((kt / 3) & 1));
        const unsigned* Kst = sm + slot * KSLOT;
        const unsigned* Vts = sm + VBASE + slot * VSLOT;

        // ---- S = Q K^T : 8 chunks x 8 nt = 64 MMA ----
        float sacc[8][4];
        #pragma unroll
        for (int nt = 0; nt < 8; nt++)
            #pragma unroll
            for (int k = 0; k < 4; k++) sacc[nt][k] = 0.f;

        #pragma unroll
        for (int gch = 0; gch < 8; gch++) {
            #pragma unroll
            for (int nt = 0; nt < 8; nt++) {
                uint2 bu = *(const uint2*)&Kst[(8 * nt + lr) * 72 + 8 * gch + 2 * lc];
                unsigned bf[2] = { bu.x, bu.y };
                mma_f16(sacc[nt], qa[gch], bf);
            }
        }

        // ---- warp-private online softmax; pack P a-frags (no shuffles) ----
        float m0 = sacc[0][0], m1 = sacc[0][2];
        #pragma unroll
        for (int nt = 0; nt < 8; nt++) {
            m0 = fmaxf(m0, fmaxf(sacc[nt][0], sacc[nt][1]));
            m1 = fmaxf(m1, fmaxf(sacc[nt][2], sacc[nt][3]));
        }
        m0 = fmaxf(m0, __shfl_xor_sync(0xffffffffu, m0, 1));
        m0 = fmaxf(m0, __shfl_xor_sync(0xffffffffu, m0, 2));
        m1 = fmaxf(m1, __shfl_xor_sync(0xffffffffu, m1, 1));
        m1 = fmaxf(m1, __shfl_xor_sync(0xffffffffu, m1, 2));
        float mn0 = fmaxf(rm0, m0), mn1 = fmaxf(rm1, m1);
        float al0 = __expf(rm0 - mn0), al1 = __expf(rm1 - mn1);
        float sum0 = 0.f, sum1 = 0.f;
        unsigned pa[4][4];
        #pragma unroll
        for (int j = 0; j < 4; j++) {
            float e00 = __expf(sacc[2 * j][0] - mn0);
            float e01 = __expf(sacc[2 * j][1] - mn0);
            float e02 = __expf(sacc[2 * j][2] - mn1);
            float e03 = __expf(sacc[2 * j][3] - mn1);
            float e10 = __expf(sacc[2 * j + 1][0] - mn0);
            float e11 = __expf(sacc[2 * j + 1][1] - mn0);
            float e12 = __expf(sacc[2 * j + 1][2] - mn1);
            float e13 = __expf(sacc[2 * j + 1][3] - mn1);
            sum0 += e00 + e01 + e10 + e11;
            sum1 += e02 + e03 + e12 + e13;
            pa[j][0] = h2pack(e00, e01);   // (row lr,   k=16j+2lc,+1)
            pa[j][1] = h2pack(e02, e03);   // (row lr+8, same k)
            pa[j][2] = h2pack(e10, e11);   // (row lr,   k=16j+8+2lc,+1)
            pa[j][3] = h2pack(e12, e13);   // (row lr+8, same k)
        }
        sum0 += __shfl_xor_sync(0xffffffffu, sum0, 1);
        sum0 += __shfl_xor_sync(0xffffffffu, sum0, 2);
        sum1 += __shfl_xor_sync(0xffffffffu, sum1, 1);
        sum1 += __shfl_xor_sync(0xffffffffu, sum1, 2);
        rl0 = rl0 * al0 + sum0;  rm0 = mn0;
        rl1 = rl1 * al1 + sum1;  rm1 = mn1;
        #pragma unroll
        for (int dt = 0; dt < 16; dt++) {
            o[dt][0] *= al0;  o[dt][1] *= al0;
            o[dt][2] *= al1;  o[dt][3] *= al1;
        }

        // ---- O += P V : 4 chunks x 16 dt = 64 MMA ----
        #pragma unroll
        for (int j = 0; j < 4; j++) {
            #pragma unroll
            for (int dt = 0; dt < 16; dt++) {
                uint2 vu = *(const uint2*)&Vts[(8 * dt + lr) * 40 + 8 * j + 2 * lc];
                unsigned bf[2] = { vu.x, vu.y };
                mma_f16(o[dt], pa[j], bf);
            }
        }

        MBAR_ARRIVE(sbase + (BARW + 6 + 2 * slot) * 4);
    }

    // Epilogue (fp32 output)
    float* Ob = O + (size_t)b * SS * DD + (size_t)h * HD;
    float inv0 = 1.f / rl0, inv1 = 1.f / rl1;
    #pragma unroll
    for (int dt = 0; dt < 16; dt++) {
        int cc = 8 * dt + 2 * lc;
        *(float2*)(Ob + (size_t)(q0 + r0) * DD + cc) =
            make_float2(o[dt][0] * inv0, o[dt][1] * inv0);
        *(float2*)(Ob + (size_t)(q0 + r0 + 8) * DD + cc) =
            make_float2(o[dt][2] * inv1, o[dt][3] * inv1);
    }
}

// ---------------------------------------------------------------------------
extern "C" void kernel_launch(void* const* d_in, const int* in_sizes, int n_in,
                              void* d_out, int out_size)
{
    (void)in_sizes; (void)n_in; (void)out_size;
    const float* H  = (const float*)d_in[0];
    const float* Wq = (const float*)d_in[1];
    const float* bq = (const float*)d_in[2];
    const float* Wk = (const float*)d_in[3];
    const float* bk = (const float*)d_in[4];
    const float* Wv = (const float*)d_in[5];
    const float* bv = (const float*)d_in[6];
    float* out = (float*)d_out;

    static cudaStream_t s2 = 0;
    static cudaEvent_t eFork = 0, eH = 0, eKV = 0;
    if (s2 == 0) {
        cudaStreamCreateWithFlags(&s2, cudaStreamNonBlocking);
        cudaEventCreateWithFlags(&eFork, cudaEventDisableTiming);
        cudaEventCreateWithFlags(&eH,    cudaEventDisableTiming);
        cudaEventCreateWithFlags(&eKV,   cudaEventDisableTiming);
    }

    __half *Qp, *Kp, *Vp, *Vtp, *Hp, *Wqp, *Wkp, *Wvp;
    cudaGetSymbolAddress((void**)&Qp,  g_Q);
    cudaGetSymbolAddress((void**)&Kp,  g_K);
    cudaGetSymbolAddress((void**)&Vp,  g_V);
    cudaGetSymbolAddress((void**)&Vtp, g_Vt);
    cudaGetSymbolAddress((void**)&Hp,  g_H);
    cudaGetSymbolAddress((void**)&Wqp, g_Wq);
    cudaGetSymbolAddress((void**)&Wkp, g_Wk);
    cudaGetSymbolAddress((void**)&Wvp, g_Wv);

    cudaFuncSetAttribute(gemm_f16,
                         cudaFuncAttributeMaxDynamicSharedMemorySize, GEMM_SMEM_BYTES);
    cudaFuncSetAttribute(attn_f16,
                         cudaFuncAttributeMaxDynamicSharedMemorySize, ATTN_SMEM_BYTES);

    const float scale = 0.08838834764831845f;  // 1/sqrt(128)
    const int nb = 148 * 8;

    // Fork s2 off the capture/main stream.
    cudaEventRecord(eFork, 0);
    cudaStreamWaitEvent(s2, eFork, 0);

    // Stream 0: H (pair-perm fp16) + Wq cvt.
    cvt_h<<<nb, 256>>>(Hp, H, (int)((size_t)MM * DD / 16));
    cvt_w<<<nb, 256>>>(Wqp, Wq, DD / 2, DD);
    cudaEventRecord(eH, 0);

    // Stream s2: Wk/Wv cvt (independent of H), then wait for H.
    cvt_w<<<nb, 256, 0, s2>>>(Wkp, Wk, DD / 2, KVD);
    cvt_w<<<nb, 256, 0, s2>>>(Wvp, Wv, DD / 2, KVD);
    cudaStreamWaitEvent(s2, eH, 0);

    // Stream 0: Q projection (z=0, exact grid).
    gemm_f16<<<dim3(DD / 256, MM / 128, 1), 256, GEMM_SMEM_BYTES>>>(
        Hp, Wqp, bq, Qp, Wkp, bk, Kp, Wvp, bv, Vp, scale, 0);

    // Stream s2: K + V projections (z=1,2), then V transpose.
    gemm_f16<<<dim3(KVD / 256, MM / 128, 2), 256, GEMM_SMEM_BYTES, s2>>>(
        Hp, Wqp, bq, Qp, Wkp, bk, Kp, Wvp, bv, Vp, scale, 1);
    transpose_v<<<dim3(SS / 64, KVD / 32, BB), dim3(32, 8), 0, s2>>>(Vtp, Vp);
    cudaEventRecord(eKV, s2);

    // Join: attention needs Q (stream 0) and K/Vt (s2).
    cudaStreamWaitEvent(0, eKV, 0);
    attn_f16<<<dim3(SS / 128, HQ, BB), 256, ATTN_SMEM_BYTES>>>(Qp, Kp, Vtp, out);
}

// round 14
// speedup vs baseline: 2.0973x; 1.0189x over previous
#include <cuda_runtime.h>
#include <cuda_fp16.h>
#include <math.h>

#define BB   2
#define SS   2048
#define DD   2048
#define HQ   16
#define HKV  4
#define HD   128
#define KVD  512
#define MM   (BB*SS)
#define NT   (SS/64)

// Scratch (device globals) — fp16 operands, fp32 I/O
__device__ __half g_Q[(size_t)MM * DD];
__device__ __half g_K[(size_t)MM * KVD];
__device__ __half g_V[(size_t)MM * KVD];
__device__ __half g_Vt[(size_t)BB * KVD * SS];
__device__ __half g_H[(size_t)MM * DD];
__device__ __half g_Wq[(size_t)DD * DD];
__device__ __half g_Wk[(size_t)DD * KVD];
__device__ __half g_Wv[(size_t)DD * KVD];

__device__ __forceinline__ unsigned h2pack(float lo, float hi) {
    __half2 h = __floats2half2_rn(lo, hi);
    return *reinterpret_cast<unsigned*>(&h);
}

__device__ __forceinline__ void mma_f16(float c[4], const unsigned a[4], const unsigned b[2]) {
    asm volatile(
        "mma.sync.aligned.m16n8k16.row.col.f32.f16.f16.f32 "
        "{%0,%1,%2,%3},{%4,%5,%6,%7},{%8,%9},{%0,%1,%2,%3};"
        : "+f"(c[0]), "+f"(c[1]), "+f"(c[2]), "+f"(c[3])
        : "r"(a[0]), "r"(a[1]), "r"(a[2]), "r"(a[3]), "r"(b[0]), "r"(b[1]));
}

#define CP16(dst, src) \
    asm volatile("cp.async.cg.shared.global [%0], [%1], 16;" :: "r"(dst), "l"(src))
#define CPCOMMIT() asm volatile("cp.async.commit_group;")
#define CPWAIT(N)  asm volatile("cp.async.wait_group %0;" :: "n"(N))

#define MBAR_INIT(addr, cnt) \
    asm volatile("mbarrier.init.shared.b64 [%0], %1;" :: "r"(addr), "r"(cnt) : "memory")
#define MBAR_ARRIVE(addr) \
    asm volatile("mbarrier.arrive.shared.b64 _, [%0];" :: "r"(addr) : "memory")
#define CPASYNC_MBAR_ARRIVE(addr) \
    asm volatile("cp.async.mbarrier.arrive.noinc.shared.b64 [%0];" :: "r"(addr) : "memory")

#define MBAR_WAIT(addr, par) do { \
    unsigned _m = (addr), _p = (par), _d; \
    asm volatile("{\n\t.reg .pred p;\n\t" \
        "mbarrier.try_wait.parity.acquire.cta.shared::cta.b64 p, [%1], %2;\n\t" \
        "selp.b32 %0, 1, 0, p;\n\t}" : "=r"(_d) : "r"(_m), "r"(_p) : "memory"); \
    if (!_d) { \
        asm volatile("{\n\t.reg .pred P1;\n\t" \
            "WL%=:\n\t" \
            "mbarrier.try_wait.parity.acquire.cta.shared::cta.b64 P1, [%0], %1, 0x989680;\n\t" \
            "@P1 bra.uni WD%=;\n\t" \
            "bra.uni WL%=;\n\t" \
            "WD%=:\n\t}" :: "r"(_m), "r"(_p) : "memory"); \
    } \
} while (0)

// ---------------------------------------------------------------------------
// H: fp32 -> fp16, pairs permuted [P0,P4,P1,P5,P2,P6,P3,P7] per 16-value group.
// ---------------------------------------------------------------------------
__global__ void cvt_h(__half* __restrict__ dst, const float* __restrict__ src, int n16)
{
    int i = blockIdx.x * blockDim.x + threadIdx.x;
    const int stride = gridDim.x * blockDim.x;
    for (; i < n16; i += stride) {
        const float4* s = (const float4*)src + 4 * (size_t)i;
        float4 s0 = s[0], s1 = s[1], s2 = s[2], s3 = s[3];
        uint4 o0, o1;
        o0.x = h2pack(s0.x, s0.y);
        o0.y = h2pack(s2.x, s2.y);
        o0.z = h2pack(s0.z, s0.w);
        o0.w = h2pack(s2.z, s2.w);
        o1.x = h2pack(s1.x, s1.y);
        o1.y = h2pack(s3.x, s3.y);
        o1.z = h2pack(s1.z, s1.w);
        o1.w = h2pack(s3.z, s3.w);
        uint4* o = (uint4*)dst + 2 * (size_t)i;
        o[0] = o0;
        o[1] = o1;
    }
}

// ---------------------------------------------------------------------------
// W: fp32 [k][n] -> h2 [k/2][n]
// ---------------------------------------------------------------------------
__global__ void cvt_w(__half* __restrict__ dst, const float* __restrict__ src,
                      int K2, int N)
{
    int j = blockIdx.x * blockDim.x + threadIdx.x;
    const int stride = gridDim.x * blockDim.x;
    const int nq = N / 4;
    const int total = K2 * nq;
    for (; j < total; j += stride) {
        int i  = j / nq;
        int n4 = (j % nq) * 4;
        float4 a = *(const float4*)(src + (size_t)(2 * i) * N + n4);
        float4 b = *(const float4*)(src + (size_t)(2 * i + 1) * N + n4);
        uint4 o;
        o.x = h2pack(a.x, b.x);
        o.y = h2pack(a.y, b.y);
        o.z = h2pack(a.z, b.z);
        o.w = h2pack(a.w, b.w);
        *((uint4*)dst + (size_t)i * nq + (n4 >> 2)) = o;
    }
}

// ---------------------------------------------------------------------------
// V half [b][s][gd] -> Vt h2 [b*512+gd][s/2], s pairs permuted per 16-s group.
// ---------------------------------------------------------------------------
__global__ void transpose_v(__half* __restrict__ Vt, const __half* __restrict__ V)
{
    __shared__ __half t[64][36];
    const int s0 = blockIdx.x * 64, gd0 = blockIdx.y * 32, b = blockIdx.z;
    #pragma unroll
    for (int i = 0; i < 8; i++) {
        int e = (threadIdx.y + i * 8) * 32 + threadIdx.x;
        int srow = e >> 5, gcol = e & 31;
        t[srow][gcol] = V[((size_t)b * SS + s0 + srow) * KVD + gd0 + gcol];
    }
    __syncthreads();
    const int x = threadIdx.x;
    const int grp = x >> 3, qq = x & 7;
    const int lp = (qq & 1) ? (qq >> 1) + 4 : (qq >> 1);
    const int sl = grp * 16 + 2 * lp;
    unsigned* Vt2 = (unsigned*)Vt;
    #pragma unroll
    for (int i = 0; i < 4; i++) {
        int gd = threadIdx.y + i * 8;
        float lo = __half2float(t[sl][gd]);
        float hi = __half2float(t[sl + 1][gd]);
        Vt2[((size_t)b * KVD + gd0 + gd) * (SS / 2) + (s0 >> 1) + x] = h2pack(lo, hi);
    }
}

// ---------------------------------------------------------------------------
// fp16 GEMM + bias: 8 warps (2m x 4n), CTA 128x256x32, 3-stage cp.async
// pipeline, ONE __syncthreads per K-iter.
// ---------------------------------------------------------------------------
#define GA 3072
#define GB 4224
#define GSTG (GA + GB)
#define GEMM_SMEM_BYTES (GSTG * 3 * 4)

__device__ __forceinline__ void gemm_stage(
    unsigned sA, unsigned sB, const __half* __restrict__ X, const unsigned* __restrict__ W2,
    int N, int bm, int bn, int k0, int tid)
{
    #pragma unroll
    for (int it = 0; it < 2; it++) {
        int f = tid + it * 256;
        int m  = f >> 2;
        int ch = f & 3;
        CP16(sA + (m * 24 + 4 * ch) * 4, X + (size_t)(bm + m) * DD + k0 + ch * 8);
    }
    const int k02 = k0 >> 1;
    #pragma unroll
    for (int it = 0; it < 4; it++) {
        int f = tid + it * 256;
        int kk2 = f >> 6;
        int nq  = (f & 63) * 4;
        CP16(sB + (kk2 * 264 + nq) * 4, W2 + (size_t)(k02 + kk2) * N + bn + nq);
    }
}

__global__ __launch_bounds__(256) void gemm_f16(
    const __half* __restrict__ X,
    const __half* __restrict__ Wq, const float* __restrict__ bq, __half* __restrict__ Yq,
    const __half* __restrict__ Wk, const float* __restrict__ bk, __half* __restrict__ Yk,
    const __half* __restrict__ Wv, const float* __restrict__ bv, __half* __restrict__ Yv,
    float qscale, int zoff)
{
    const int z = blockIdx.z + zoff;
    const __half* __restrict__ W  = (z == 0) ? Wq : (z == 1) ? Wk : Wv;
    const float*  __restrict__ bi = (z == 0) ? bq : (z == 1) ? bk : bv;
    __half*       __restrict__ Y  = (z == 0) ? Yq : (z == 1) ? Yk : Yv;
    const int   N      = (z == 0) ? DD : KVD;
    const float oscale = (z == 0) ? qscale : 1.0f;
    const int   permv  = (z == 2) ? 0 : 1;

    extern __shared__ unsigned smg[];
    const int tid  = threadIdx.x;
    const int lane = tid & 31;
    const int wid  = tid >> 5;
    const int wm   = wid >> 2;
    const int wn   = wid & 3;
    const int lr   = lane >> 2;
    const int lc   = lane & 3;
    const int bm = blockIdx.y * 128;
    const int bn = blockIdx.x * 256;

    unsigned sbase = (unsigned)__cvta_generic_to_shared(smg);

    float acc[4][8][4];
    #pragma unroll
    for (int i = 0; i < 4; i++)
        #pragma unroll
        for (int j = 0; j < 8; j++)
            #pragma unroll
            for (int k = 0; k < 4; k++) acc[i][j][k] = 0.f;

    const int nK = DD / 32;
    gemm_stage(sbase, sbase + GA * 4, X, (const unsigned*)W, N, bm, bn, 0, tid);
    CPCOMMIT();
    gemm_stage(sbase + GSTG * 4, sbase + (GSTG + GA) * 4,
               X, (const unsigned*)W, N, bm, bn, 32, tid);
    CPCOMMIT();

    for (int i = 0; i < nK; i++) {
        if (i + 1 < nK) { CPWAIT(1); } else { CPWAIT(0); }
        __syncthreads();
        if (i + 2 < nK) {
            unsigned boff = ((i + 2) % 3) * GSTG * 4;
            gemm_stage(sbase + boff, sbase + boff + GA * 4,
                       X, (const unsigned*)W, N, bm, bn, (i + 2) * 32, tid);
            CPCOMMIT();
        }
        const unsigned* As = smg + (i % 3) * GSTG;
        const unsigned* Bs = As + GA;

        #pragma unroll
        for (int g = 0; g < 2; g++) {
            unsigned af[4][4], bf[8][2];
            #pragma unroll
            for (int mt = 0; mt < 4; mt++) {
                int r = wm * 64 + mt * 16 + lr;
                uint2 u1 = *(const uint2*)&As[r * 24 + 8 * g + 2 * lc];
                uint2 u2 = *(const uint2*)&As[(r + 8) * 24 + 8 * g + 2 * lc];
                af[mt][0] = u1.x; af[mt][1] = u2.x;
                af[mt][2] = u1.y; af[mt][3] = u2.y;
            }
            #pragma unroll
            for (int nt = 0; nt < 8; nt++) {
                int n = wn * 64 + nt * 8 + lr;
                bf[nt][0] = Bs[(8 * g + lc) * 264 + n];
                bf[nt][1] = Bs[(8 * g + lc + 4) * 264 + n];
            }
            #pragma unroll
            for (int mt = 0; mt < 4; mt++)
                #pragma unroll
                for (int nt = 0; nt < 8; nt++)
                    mma_f16(acc[mt][nt], af[mt], bf[nt]);
        }
    }

    #pragma unroll
    for (int mt = 0; mt < 4; mt++) {
        int r = bm + wm * 64 + mt * 16 + lr;
        #pragma unroll
        for (int nt = 0; nt < 8; nt++) {
            int base = bn + wn * 64 + nt * 8;
            int c0 = base + 2 * lc;
            float bv0 = bi[c0], bv1 = bi[c0 + 1];
            unsigned v0 = h2pack((acc[mt][nt][0] + bv0) * oscale,
                                 (acc[mt][nt][1] + bv1) * oscale);
            unsigned v1 = h2pack((acc[mt][nt][2] + bv0) * oscale,
                                 (acc[mt][nt][3] + bv1) * oscale);
            int idx;
            if (permv) {
                int L = (c0 & 15) >> 1;
                int phys = (L < 4) ? 2 * L : 2 * L - 7;
                idx = (c0 & ~15) + 2 * phys;
            } else {
                idx = c0;
            }
            *(unsigned*)(Y + (size_t)r * N + idx) = v0;
            *(unsigned*)(Y + (size_t)(r + 8) * N + idx) = v1;
        }
    }
}

// ---------------------------------------------------------------------------
// fp16 flash attention, 128-key softmax blocks. 128 q-rows/CTA, 8 warps x
// 16 rows; K/Vt quad-buffered 64-key slots, combined per-slot full/empty
// mbarriers; each outer iter consumes TWO slots with ONE softmax pass.
// SMEM words: K 4x4608=18432 | Vt 4x5120=20480 | 16 barrier words.
// ---------------------------------------------------------------------------
#define KSLOT 4608
#define VSLOT 5120
#define VBASE 18432
#define BARW  38912
#define ATTN_SMEM_BYTES (38944 * 4)

__global__ __launch_bounds__(256) void attn_f16(
    const __half* __restrict__ Q, const __half* __restrict__ K,
    const __half* __restrict__ Vt, float* __restrict__ O)
{
    extern __shared__ unsigned sm[];

    const int tid  = threadIdx.x;
    const int lane = tid & 31;
    const int wid  = tid >> 5;
    const int lr = lane >> 2;
    const int lc = lane & 3;
    const int r0 = 16 * wid + lr;
    const int q0 = blockIdx.x * 128;
    const int h  = blockIdx.y;
    const int b  = blockIdx.z;
    const int g  = h & (HKV - 1);

    const __half* Qb = Q + (size_t)b * SS * DD  + (size_t)h * HD;
    const __half* Kb = K + (size_t)b * SS * KVD + (size_t)g * HD;
    const unsigned* Vb2 = (const unsigned*)Vt + ((size_t)b * KVD + (size_t)g * HD) * (SS / 2);

    unsigned sbase = (unsigned)__cvta_generic_to_shared(sm);
    // full[s] @ BARW+2s ; empty[s] @ BARW+8+2s   (s = 0..3)

    if (tid == 0) {
        #pragma unroll
        for (int s = 0; s < 4; s++) {
            MBAR_INIT(sbase + (BARW + 2 * s) * 4, 256);
            MBAR_INIT(sbase + (BARW + 8 + 2 * s) * 4, 256);
        }
    }

    // --- Prologue: stage Q through K slots 0-1 region, move to registers ---
    #pragma unroll
    for (int it = 0; it < 8; it++) {
        int f = tid + it * 256;
        int q  = f >> 4;
        int ch = f & 15;
        CP16(sbase + (q * 72 + 4 * ch) * 4, Qb + (size_t)(q0 + q) * DD + ch * 8);
    }
    CPCOMMIT();
    CPWAIT(0);
    __syncthreads();

    unsigned qa[8][4];
    #pragma unroll
    for (int gch = 0; gch < 8; gch++) {
        uint2 u1 = *(const uint2*)&sm[r0 * 72 + 8 * gch + 2 * lc];
        uint2 u2 = *(const uint2*)&sm[(r0 + 8) * 72 + 8 * gch + 2 * lc];
        qa[gch][0] = u1.x; qa[gch][1] = u2.x;
        qa[gch][2] = u1.y; qa[gch][3] = u2.y;
    }
    __syncthreads();

    // --- Fill tiles 0,1 (slots 0,1) ---
    #pragma unroll
    for (int s = 0; s < 2; s++) {
        unsigned sKs = sbase + s * KSLOT * 4;
        unsigned sVs = sbase + (VBASE + s * VSLOT) * 4;
        #pragma unroll
        for (int it = 0; it < 4; it++) {
            int f = tid + it * 256;
            int key = f >> 4;
            int ch  = f & 15;
            CP16(sKs + (key * 72 + 4 * ch) * 4,
                 Kb + (size_t)(s * 64 + key) * KVD + ch * 8);
        }
        #pragma unroll
        for (int it = 0; it < 4; it++) {
            int f = tid + it * 256;
            int d  = f >> 3;
            int ch = f & 7;
            CP16(sVs + (d * 40 + 4 * ch) * 4,
                 Vb2 + (size_t)d * (SS / 2) + s * 32 + ch * 4);
        }
        CPASYNC_MBAR_ARRIVE(sbase + (BARW + 2 * s) * 4);
    }

    float o[16][4];
    #pragma unroll
    for (int dt = 0; dt < 16; dt++)
        #pragma unroll
        for (int k = 0; k < 4; k++) o[dt][k] = 0.f;
    float rm0 = -INFINITY, rm1 = -INFINITY, rl0 = 0.f, rl1 = 0.f;

    #pragma unroll 1
    for (int j = 0; j < NT / 2; j++) {
        // --- producer: fill tiles 2j+2, 2j+3 ---
        #pragma unroll
        for (int pp = 0; pp < 2; pp++) {
            const int ft = 2 * j + 2 + pp;
            if (ft < NT) {
                const int slot = ft & 3;
                if (ft >= 4) MBAR_WAIT(sbase + (BARW + 8 + 2 * slot) * 4,
                                       (unsigned)(((ft >> 2) - 1) & 1));
                unsigned sKs = sbase + slot * KSLOT * 4;
                unsigned sVs = sbase + (VBASE + slot * VSLOT) * 4;
                #pragma unroll
                for (int it = 0; it < 4; it++) {
                    int f = tid + it * 256;
                    int key = f >> 4;
                    int ch  = f & 15;
                    CP16(sKs + (key * 72 + 4 * ch) * 4,
                         Kb + (size_t)(ft * 64 + key) * KVD + ch * 8);
                }
                #pragma unroll
                for (int it = 0; it < 4; it++) {
                    int f = tid + it * 256;
                    int d  = f >> 3;
                    int ch = f & 7;
                    CP16(sVs + (d * 40 + 4 * ch) * 4,
                         Vb2 + (size_t)d * (SS / 2) + ft * 32 + ch * 4);
                }
                CPASYNC_MBAR_ARRIVE(sbase + (BARW + 2 * slot) * 4);
            }
        }

        const int t0 = 2 * j;
        const int s0 = t0 & 3, s1 = (t0 + 1) & 3;
        const unsigned par = (unsigned)((t0 >> 2) & 1);

        // ---- S_A = Q K(t0)^T ----
        MBAR_WAIT(sbase + (BARW + 2 * s0) * 4, par);
        const unsigned* KstA = sm + s0 * KSLOT;
        float saccA[8][4];
        #pragma unroll
        for (int nt = 0; nt < 8; nt++)
            #pragma unroll
            for (int k = 0; k < 4; k++) saccA[nt][k] = 0.f;
        #pragma unroll
        for (int gch = 0; gch < 8; gch++) {
            #pragma unroll
            for (int nt = 0; nt < 8; nt++) {
                uint2 bu = *(const uint2*)&KstA[(8 * nt + lr) * 72 + 8 * gch + 2 * lc];
                unsigned bf[2] = { bu.x, bu.y };
                mma_f16(saccA[nt], qa[gch], bf);
            }
        }

        // ---- S_B = Q K(t0+1)^T ----
        MBAR_WAIT(sbase + (BARW + 2 * s1) * 4, par);
        const unsigned* KstB = sm + s1 * KSLOT;
        float saccB[8][4];
        #pragma unroll
        for (int nt = 0; nt < 8; nt++)
            #pragma unroll
            for (int k = 0; k < 4; k++) saccB[nt][k] = 0.f;
        #pragma unroll
        for (int gch = 0; gch < 8; gch++) {
            #pragma unroll
            for (int nt = 0; nt < 8; nt++) {
                uint2 bu = *(const uint2*)&KstB[(8 * nt + lr) * 72 + 8 * gch + 2 * lc];
                unsigned bf[2] = { bu.x, bu.y };
                mma_f16(saccB[nt], qa[gch], bf);
            }
        }

        // ---- joint softmax over 128 keys ----
        float m0 = saccA[0][0], m1 = saccA[0][2];
        #pragma unroll
        for (int nt = 0; nt < 8; nt++) {
            m0 = fmaxf(m0, fmaxf(saccA[nt][0], saccA[nt][1]));
            m1 = fmaxf(m1, fmaxf(saccA[nt][2], saccA[nt][3]));
            m0 = fmaxf(m0, fmaxf(saccB[nt][0], saccB[nt][1]));
            m1 = fmaxf(m1, fmaxf(saccB[nt][2], saccB[nt][3]));
        }
        m0 = fmaxf(m0, __shfl_xor_sync(0xffffffffu, m0, 1));
        m0 = fmaxf(m0, __shfl_xor_sync(0xffffffffu, m0, 2));
        m1 = fmaxf(m1, __shfl_xor_sync(0xffffffffu, m1, 1));
        m1 = fmaxf(m1, __shfl_xor_sync(0xffffffffu, m1, 2));
        float mn0 = fmaxf(rm0, m0), mn1 = fmaxf(rm1, m1);
        float al0 = __expf(rm0 - mn0), al1 = __expf(rm1 - mn1);
        float sum0 = 0.f, sum1 = 0.f;
        unsigned paA[4][4], paB[4][4];
        #pragma unroll
        for (int jj = 0; jj < 4; jj++) {
            float e00 = __expf(saccA[2 * jj][0] - mn0);
            float e01 = __expf(saccA[2 * jj][1] - mn0);
            float e02 = __expf(saccA[2 * jj][2] - mn1);
            float e03 = __expf(saccA[2 * jj][3] - mn1);
            float e10 = __expf(saccA[2 * jj + 1][0] - mn0);
            float e11 = __expf(saccA[2 * jj + 1][1] - mn0);
            float e12 = __expf(saccA[2 * jj + 1][2] - mn1);
            float e13 = __expf(saccA[2 * jj + 1][3] - mn1);
            sum0 += e00 + e01 + e10 + e11;
            sum1 += e02 + e03 + e12 + e13;
            paA[jj][0] = h2pack(e00, e01);
            paA[jj][1] = h2pack(e02, e03);
            paA[jj][2] = h2pack(e10, e11);
            paA[jj][3] = h2pack(e12, e13);
        }
        #pragma unroll
        for (int jj = 0; jj < 4; jj++) {
            float e00 = __expf(saccB[2 * jj][0] - mn0);
            float e01 = __expf(saccB[2 * jj][1] - mn0);
            float e02 = __expf(saccB[2 * jj][2] - mn1);
            float e03 = __expf(saccB[2 * jj][3] - mn1);
            float e10 = __expf(saccB[2 * jj + 1][0] - mn0);
            float e11 = __expf(saccB[2 * jj + 1][1] - mn0);
            float e12 = __expf(saccB[2 * jj + 1][2] - mn1);
            float e13 = __expf(saccB[2 * jj + 1][3] - mn1);
            sum0 += e00 + e01 + e10 + e11;
            sum1 += e02 + e03 + e12 + e13;
            paB[jj][0] = h2pack(e00, e01);
            paB[jj][1] = h2pack(e02, e03);
            paB[jj][2] = h2pack(e10, e11);
            paB[jj][3] = h2pack(e12, e13);
        }
        sum0 += __shfl_xor_sync(0xffffffffu, sum0, 1);
        sum0 += __shfl_xor_sync(0xffffffffu, sum0, 2);
        sum1 += __shfl_xor_sync(0xffffffffu, sum1, 1);
        sum1 += __shfl_xor_sync(0xffffffffu, sum1, 2);
        rl0 = rl0 * al0 + sum0;  rm0 = mn0;
        rl1 = rl1 * al1 + sum1;  rm1 = mn1;
        #pragma unroll
        for (int dt = 0; dt < 16; dt++) {
            o[dt][0] *= al0;  o[dt][1] *= al0;
            o[dt][2] *= al1;  o[dt][3] *= al1;
        }

        // ---- O += P_A V(t0) ----
        const unsigned* VtsA = sm + VBASE + s0 * VSLOT;
        #pragma unroll
        for (int jj = 0; jj < 4; jj++) {
            #pragma unroll
            for (int dt = 0; dt < 16; dt++) {
                uint2 vu = *(const uint2*)&VtsA[(8 * dt + lr) * 40 + 8 * jj + 2 * lc];
                unsigned bf[2] = { vu.x, vu.y };
                mma_f16(o[dt], paA[jj], bf);
            }
        }
        MBAR_ARRIVE(sbase + (BARW + 8 + 2 * s0) * 4);

        // ---- O += P_B V(t0+1) ----
        const unsigned* VtsB = sm + VBASE + s1 * VSLOT;
        #pragma unroll
        for (int jj = 0; jj < 4; jj++) {
            #pragma unroll
            for (int dt = 0; dt < 16; dt++) {
                uint2 vu = *(const uint2*)&VtsB[(8 * dt + lr) * 40 + 8 * jj + 2 * lc];
                unsigned bf[2] = { vu.x, vu.y };
                mma_f16(o[dt], paB[jj], bf);
            }
        }
        MBAR_ARRIVE(sbase + (BARW + 8 + 2 * s1) * 4);
    }

    // Epilogue (fp32 output)
    float* Ob = O + (size_t)b * SS * DD + (size_t)h * HD;
    float inv0 = 1.f / rl0, inv1 = 1.f / rl1;
    #pragma unroll
    for (int dt = 0; dt < 16; dt++) {
        int cc = 8 * dt + 2 * lc;
        *(float2*)(Ob + (size_t)(q0 + r0) * DD + cc) =
            make_float2(o[dt][0] * inv0, o[dt][1] * inv0);
        *(float2*)(Ob + (size_t)(q0 + r0 + 8) * DD + cc) =
            make_float2(o[dt][2] * inv1, o[dt][3] * inv1);
    }
}

// ---------------------------------------------------------------------------
extern "C" void kernel_launch(void* const* d_in, const int* in_sizes, int n_in,
                              void* d_out, int out_size)
{
    (void)in_sizes; (void)n_in; (void)out_size;
    const float* H  = (const float*)d_in[0];
    const float* Wq = (const float*)d_in[1];
    const float* bq = (const float*)d_in[2];
    const float* Wk = (const float*)d_in[3];
    const float* bk = (const float*)d_in[4];
    const float* Wv = (const float*)d_in[5];
    const float* bv = (const float*)d_in[6];
    float* out = (float*)d_out;

    static cudaStream_t s2 = 0;
    static cudaEvent_t eFork = 0, eH = 0, eKV = 0;
    if (s2 == 0) {
        cudaStreamCreateWithFlags(&s2, cudaStreamNonBlocking);
        cudaEventCreateWithFlags(&eFork, cudaEventDisableTiming);
        cudaEventCreateWithFlags(&eH,    cudaEventDisableTiming);
        cudaEventCreateWithFlags(&eKV,   cudaEventDisableTiming);
    }

    __half *Qp, *Kp, *Vp, *Vtp, *Hp, *Wqp, *Wkp, *Wvp;
    cudaGetSymbolAddress((void**)&Qp,  g_Q);
    cudaGetSymbolAddress((void**)&Kp,  g_K);
    cudaGetSymbolAddress((void**)&Vp,  g_V);
    cudaGetSymbolAddress((void**)&Vtp, g_Vt);
    cudaGetSymbolAddress((void**)&Hp,  g_H);
    cudaGetSymbolAddress((void**)&Wqp, g_Wq);
    cudaGetSymbolAddress((void**)&Wkp, g_Wk);
    cudaGetSymbolAddress((void**)&Wvp, g_Wv);

    cudaFuncSetAttribute(gemm_f16,
                         cudaFuncAttributeMaxDynamicSharedMemorySize, GEMM_SMEM_BYTES);
    cudaFuncSetAttribute(attn_f16,
                         cudaFuncAttributeMaxDynamicSharedMemorySize, ATTN_SMEM_BYTES);

    const float scale = 0.08838834764831845f;  // 1/sqrt(128)
    const int nb = 148 * 8;

    cudaEventRecord(eFork, 0);
    cudaStreamWaitEvent(s2, eFork, 0);

    cvt_h<<<nb, 256>>>(Hp, H, (int)((size_t)MM * DD / 16));
    cvt_w<<<nb, 256>>>(Wqp, Wq, DD / 2, DD);
    cudaEventRecord(eH, 0);

    cvt_w<<<nb, 256, 0, s2>>>(Wkp, Wk, DD / 2, KVD);
    cvt_w<<<nb, 256, 0, s2>>>(Wvp, Wv, DD / 2, KVD);
    cudaStreamWaitEvent(s2, eH, 0);

    gemm_f16<<<dim3(DD / 256, MM / 128, 1), 256, GEMM_SMEM_BYTES>>>(
        Hp, Wqp, bq, Qp, Wkp, bk, Kp, Wvp, bv, Vp, scale, 0);

    gemm_f16<<<dim3(KVD / 256, MM / 128, 2), 256, GEMM_SMEM_BYTES, s2>>>(
        Hp, Wqp, bq, Qp, Wkp, bk, Kp, Wvp, bv, Vp, scale, 1);
    transpose_v<<<dim3(SS / 64, KVD / 32, BB), dim3(32, 8), 0, s2>>>(Vtp, Vp);
    cudaEventRecord(eKV, s2);

    cudaStreamWaitEvent(0, eKV, 0);
    attn_f16<<<dim3(SS / 128, HQ, BB), 256, ATTN_SMEM_BYTES>>>(Qp, Kp, Vtp, out);
}